// round 4
// baseline (speedup 1.0000x reference)
#include <cuda_runtime.h>

#define N_NODES 20000
#define N_EDGES 60000
#define NODE_IN 8
#define HID     64
#define BATCH   256
#define MLP_H   128
#define N_ACT   20000

#define NT   16      // nodes per block in nnconv
#define OC   8       // output-column chunk
#define TCAP 1024    // edge-task list capacity per block

// ---------------- device scratch ----------------
__device__ float d_h1e[N_EDGES * HID];
__device__ float d_h2e[N_EDGES * HID];
__device__ float d_deg[N_NODES];
__device__ float d_agg1[N_NODES * HID];
__device__ float d_h1[N_NODES * HID];
__device__ float d_agg2[N_NODES * HID];
__device__ float d_colsum[HID];
__device__ float d_g[HID];
__device__ float d_y1[BATCH * MLP_H];
__device__ float d_z1[BATCH * MLP_H];
__device__ float d_z2[BATCH * MLP_H];
// CSR by src
__device__ int d_srccnt[N_NODES];
__device__ int d_fill[N_NODES];
__device__ int d_srcptr[N_NODES + 1];
__device__ int d_elist[N_EDGES];

// ---------------- zero scratch ----------------
__global__ void zero_kernel() {
    int i  = blockIdx.x * blockDim.x + threadIdx.x;
    int gs = gridDim.x * blockDim.x;
    for (int j = i; j < N_NODES * HID; j += gs) { d_agg1[j] = 0.f; d_agg2[j] = 0.f; }
    for (int j = i; j < N_NODES; j += gs) { d_deg[j] = 0.f; d_srccnt[j] = 0; d_fill[j] = 0; }
    for (int j = i; j < BATCH * MLP_H; j += gs) d_y1[j] = 0.f;
    if (i < HID) d_colsum[i] = 0.f;
}

// ---------------- edge feature MLPs + degree counts ----------------
__global__ void edge_feat_kernel(const float* __restrict__ edge_attr,
                                 const int*   __restrict__ edge_index,
                                 const float* __restrict__ W1a, const float* __restrict__ b1a,
                                 const float* __restrict__ W1b, const float* __restrict__ b1b) {
    __shared__ float wa[256], wb[256], ba[64], bb[64], ea[4][4];
    int tid = threadIdx.x;
    wa[tid] = W1a[tid];
    wb[tid] = W1b[tid];
    if (tid < 64) { ba[tid] = b1a[tid]; bb[tid] = b1b[tid]; }
    int e0 = blockIdx.x * 4;
    if (tid < 16) {
        int le = tid >> 2, j = tid & 3;
        int e = e0 + le;
        ea[le][j] = (e < N_EDGES) ? edge_attr[e * 4 + j] : 0.f;
    }
    __syncthreads();
    int c = tid & 63, le = tid >> 6, e = e0 + le;
    if (e < N_EDGES) {
        float s1 = ba[c], s2 = bb[c];
#pragma unroll
        for (int j = 0; j < 4; j++) {
            s1 += ea[le][j] * wa[j * 64 + c];
            s2 += ea[le][j] * wb[j * 64 + c];
        }
        d_h1e[e * 64 + c] = fmaxf(s1, 0.f);
        d_h2e[e * 64 + c] = fmaxf(s2, 0.f);
        if (c == 0) atomicAdd(&d_deg[edge_index[N_EDGES + e]], 1.f);
        if (c == 1) atomicAdd(&d_srccnt[edge_index[e]], 1);
    }
}

// ---------------- exclusive scan of src counts (single block) ----------------
__global__ void scan_kernel() {
    __shared__ int part[512];
    int tid = threadIdx.x;
    const int CH = (N_NODES + 511) / 512;   // 40
    int base = tid * CH;
    int s = 0;
    for (int j = 0; j < CH; j++) {
        int idx = base + j;
        if (idx < N_NODES) s += d_srccnt[idx];
    }
    part[tid] = s;
    __syncthreads();
    for (int off = 1; off < 512; off <<= 1) {
        int v = (tid >= off) ? part[tid - off] : 0;
        __syncthreads();
        part[tid] += v;
        __syncthreads();
    }
    int run = (tid > 0) ? part[tid - 1] : 0;
    for (int j = 0; j < CH; j++) {
        int idx = base + j;
        if (idx < N_NODES) { d_srcptr[idx] = run; run += d_srccnt[idx]; }
    }
    if (tid == 511) d_srcptr[N_NODES] = run;
}

// ---------------- scatter edges into CSR lists ----------------
__global__ void scatter_kernel(const int* __restrict__ edge_index) {
    int e = blockIdx.x * 256 + threadIdx.x;
    if (e < N_EDGES) {
        int s = edge_index[e];
        int pos = d_srcptr[s] + atomicAdd(&d_fill[s], 1);
        d_elist[pos] = e;
    }
}

// ---------------- per-edge consume body (shared by main & fallback path) ----------------
__device__ __forceinline__ void consume_edge(int packed, const float* __restrict__ hE,
                                             const int* __restrict__ dstp,
                                             float* __restrict__ agg,
                                             const float* __restrict__ Mns,
                                             const float* __restrict__ bn,
                                             float* hEs_w, int l, int o0) {
    int ln = packed >> 24;
    int e  = packed & 0xFFFFFF;
    hEs_w[l]      = hE[e * 64 + l];
    hEs_w[l + 32] = hE[e * 64 + 32 + l];
    __syncwarp();
    int o = l & 7, p = l >> 3;
    const float* mp = &Mns[(ln * 64 + p * 16) * 9 + o];
    const float* hp = &hEs_w[p * 16];
    float s = 0.f;
#pragma unroll
    for (int j = 0; j < 16; j++) s += hp[j] * mp[j * 9];
    s += __shfl_xor_sync(0xFFFFFFFFu, s, 8);
    s += __shfl_xor_sync(0xFFFFFFFFu, s, 16);
    if (p == 0) {
        int d = dstp[e];
        atomicAdd(&agg[d * 64 + o0 + o], s + bn[ln * 68 + o0 + o]);
    }
    __syncwarp();
}

// ---------------- NNConv: per-NODE weight GEMM fused with edge consumption ----------------
// Mn[n,k,o] = sum_i xin[n,i]*W2[k, i*64+o]   (computed in register tiles, o-chunked)
// msg[e,o]  = sum_k hE[e,k]*Mn[src_e,k,o] + bn[src_e,o]  -> atomic into agg[dst]
template<int IDIM>
__launch_bounds__(256, 2)
__global__ void nnconv_kernel(const float* __restrict__ xin_param,
                              const float* __restrict__ W2,
                              const float* __restrict__ b2,
                              const int*   __restrict__ edge_index) {
    const float* xin = (IDIM == 8) ? xin_param : d_h1;
    const float* hE  = (IDIM == 8) ? d_h1e : d_h2e;
    float*       agg = (IDIM == 8) ? d_agg1 : d_agg2;
    const int*   dstp = edge_index + N_EDGES;

    constexpr int XROW = IDIM + 1;
    constexpr int WROW = IDIM * 64;

    extern __shared__ float sm[];
    float* xs   = sm;                        // [NT][XROW]
    float* Wss  = xs + NT * XROW;            // [8][64][8] = 4096 (16B aligned)
    float* Mns  = Wss + 4096;                // [NT][64][9] = 9216
    float* bn   = Mns + 9216;                // [NT][68] = 1088
    float* hEs  = bn + 1088;                 // [8 warps][68] = 544
    int*   tasks = (int*)(hEs + 544);        // [TCAP]
    int*   soff  = tasks + TCAP;             // [NT+1]

    int tid = threadIdx.x;
    int nb0 = blockIdx.x * NT;

    // gather node features
    for (int idx = tid; idx < NT * IDIM; idx += 256) {
        int ln = idx / IDIM, i = idx % IDIM;
        int n = nb0 + ln;
        xs[ln * XROW + i] = (n < N_NODES) ? xin[n * IDIM + i] : 0.f;
    }
    // build task list offsets
    if (tid == 0) {
        int o = 0;
        for (int ln = 0; ln < NT; ln++) {
            int n = nb0 + ln;
            soff[ln] = o;
            if (n < N_NODES) o += d_srcptr[n + 1] - d_srcptr[n];
        }
        soff[NT] = o;
    }
    // stage b2 into Mns region temporarily
    for (int idx = tid; idx < IDIM * 64; idx += 256) Mns[idx] = b2[idx];
    __syncthreads();
    int ntask = soff[NT];
    // fill task list
    if (tid < NT) {
        int n = nb0 + tid;
        if (n < N_NODES) {
            int b = d_srcptr[n];
            int c = d_srcptr[n + 1] - b;
            int o = soff[tid];
            for (int j = 0; j < c && o + j < TCAP; j++)
                tasks[o + j] = (tid << 24) | d_elist[b + j];
        }
    }
    // bnode[n][o] = sum_i xs[n][i]*b2[i*64+o]
    for (int idx = tid; idx < NT * 64; idx += 256) {
        int ln = idx >> 6, o = idx & 63;
        float s = 0.f;
#pragma unroll 8
        for (int i = 0; i < IDIM; i++) s += xs[ln * XROW + i] * Mns[i * 64 + o];
        bn[ln * 68 + o] = s;
    }

    int k = tid & 63;
    int g = tid >> 6;      // node group: nodes g*4 .. g*4+3
    int w = tid >> 5, l = tid & 31;
    int cap = (ntask < TCAP) ? ntask : TCAP;

    for (int oc = 0; oc < 64 / OC; oc++) {
        int o0 = oc * OC;
        float acc[4][8];
#pragma unroll
        for (int a = 0; a < 4; a++)
#pragma unroll
            for (int o = 0; o < 8; o++) acc[a][o] = 0.f;

        for (int is = 0; is < IDIM / 8; is++) {
            __syncthreads();   // Wss (and first iter: Mns consumers) safe to overwrite
            for (int idx = tid; idx < 4096; idx += 256) {
                int i = idx >> 9, kk = (idx >> 3) & 63, o = idx & 7;
                Wss[idx] = W2[kk * WROW + (is * 8 + i) * 64 + o0 + o];
            }
            __syncthreads();
#pragma unroll
            for (int ii = 0; ii < 8; ii++) {
                int i = is * 8 + ii;
                float h0 = xs[(g * 4 + 0) * XROW + i];
                float h1 = xs[(g * 4 + 1) * XROW + i];
                float h2 = xs[(g * 4 + 2) * XROW + i];
                float h3 = xs[(g * 4 + 3) * XROW + i];
                const float* wp = &Wss[ii * 512 + k * 8];
                float4 wA = *(const float4*)wp;
                float4 wB = *(const float4*)(wp + 4);
                acc[0][0] += h0 * wA.x; acc[0][1] += h0 * wA.y; acc[0][2] += h0 * wA.z; acc[0][3] += h0 * wA.w;
                acc[0][4] += h0 * wB.x; acc[0][5] += h0 * wB.y; acc[0][6] += h0 * wB.z; acc[0][7] += h0 * wB.w;
                acc[1][0] += h1 * wA.x; acc[1][1] += h1 * wA.y; acc[1][2] += h1 * wA.z; acc[1][3] += h1 * wA.w;
                acc[1][4] += h1 * wB.x; acc[1][5] += h1 * wB.y; acc[1][6] += h1 * wB.z; acc[1][7] += h1 * wB.w;
                acc[2][0] += h2 * wA.x; acc[2][1] += h2 * wA.y; acc[2][2] += h2 * wA.z; acc[2][3] += h2 * wA.w;
                acc[2][4] += h2 * wB.x; acc[2][5] += h2 * wB.y; acc[2][6] += h2 * wB.z; acc[2][7] += h2 * wB.w;
                acc[3][0] += h3 * wA.x; acc[3][1] += h3 * wA.y; acc[3][2] += h3 * wA.z; acc[3][3] += h3 * wA.w;
                acc[3][4] += h3 * wB.x; acc[3][5] += h3 * wB.y; acc[3][6] += h3 * wB.z; acc[3][7] += h3 * wB.w;
            }
        }
        // write Mn chunk to smem: Mns[n][k][o], row pad 9
#pragma unroll
        for (int a = 0; a < 4; a++) {
            float* mp = &Mns[((g * 4 + a) * 64 + k) * 9];
#pragma unroll
            for (int o = 0; o < 8; o++) mp[o] = acc[a][o];
        }
        __syncthreads();

        // edge consumption: one warp per edge task
        float* hw = &hEs[w * 68];
        for (int t = w; t < cap; t += 8)
            consume_edge(tasks[t], hE, dstp, agg, Mns, bn, hw, l, o0);
        if (ntask > TCAP) {   // pathological overflow fallback (never hit on this dataset)
            for (int t = TCAP + w; t < ntask; t += 8) {
                int ln = 0;
                while (soff[ln + 1] <= t) ln++;
                int e = d_elist[d_srcptr[nb0 + ln] + (t - soff[ln])];
                consume_edge((ln << 24) | e, hE, dstp, agg, Mns, bn, hw, l, o0);
            }
        }
        __syncthreads();
    }
}

// ---------------- node update 1 ----------------
__global__ void node_update1(const float* __restrict__ x,
                             const float* __restrict__ root1,
                             const float* __restrict__ bias1) {
    __shared__ float r1[512], b1s[64], xs[4][8], dn[4];
    int tid = threadIdx.x;
    r1[tid] = root1[tid];
    r1[tid + 256] = root1[tid + 256];
    if (tid < 64) b1s[tid] = bias1[tid];
    int n0 = blockIdx.x * 4;
    if (tid < 32) {
        int ln = tid >> 3, j = tid & 7;
        int n = n0 + ln;
        xs[ln][j] = (n < N_NODES) ? x[n * 8 + j] : 0.f;
    }
    if (tid < 4) {
        int n = n0 + tid;
        dn[tid] = (n < N_NODES) ? fmaxf(d_deg[n], 1.f) : 1.f;
    }
    __syncthreads();
    int c = tid & 63, ln = tid >> 6, n = n0 + ln;
    if (n < N_NODES) {
        float s = d_agg1[n * 64 + c] / dn[ln] + b1s[c];
#pragma unroll
        for (int j = 0; j < 8; j++) s += xs[ln][j] * r1[j * 64 + c];
        d_h1[n * 64 + c] = fmaxf(s, 0.f);
    }
}

// ---------------- node update 2 + column sums for mean pool ----------------
__global__ void node_update2(const float* __restrict__ root2,
                             const float* __restrict__ bias2) {
    __shared__ float h1s[64 * 65];
    __shared__ float r2s[64 * 64];
    __shared__ float b2s[64];
    __shared__ float dn[64];
    __shared__ float colpart[4 * 64];
    int tid = threadIdx.x;
    int n0 = blockIdx.x * 64;
    for (int idx = tid; idx < 64 * 64; idx += 256) r2s[idx] = root2[idx];
    for (int idx = tid; idx < 64 * 64; idx += 256) {
        int ln = idx >> 6, kk = idx & 63;
        int n = n0 + ln;
        h1s[ln * 65 + kk] = (n < N_NODES) ? d_h1[n * 64 + kk] : 0.f;
    }
    if (tid < 64) {
        b2s[tid] = bias2[tid];
        int n = n0 + tid;
        dn[tid] = (n < N_NODES) ? fmaxf(d_deg[n], 1.f) : 1.f;
    }
    __syncthreads();
    int c = tid & 63, ng = tid >> 6;
    float csum = 0.f;
    for (int j = 0; j < 16; j++) {
        int ln = ng + 4 * j;
        int n = n0 + ln;
        if (n < N_NODES) {
            float s = d_agg2[n * 64 + c] / dn[ln] + b2s[c];
#pragma unroll 8
            for (int kk = 0; kk < 64; kk++) s += h1s[ln * 65 + kk] * r2s[kk * 64 + c];
            csum += fmaxf(s, 0.f);
        }
    }
    colpart[ng * 64 + c] = csum;
    __syncthreads();
    if (tid < 64) {
        float t = colpart[tid] + colpart[64 + tid] + colpart[128 + tid] + colpart[192 + tid];
        atomicAdd(&d_colsum[tid], t);
    }
}

// ---------------- g vector ----------------
__global__ void g_kernel(const float* __restrict__ projW, const float* __restrict__ projb) {
    __shared__ float cs[64];
    int tid = threadIdx.x;
    cs[tid] = d_colsum[tid] * (1.f / (float)N_NODES);
    __syncthreads();
    float s = projb[tid];
    for (int c = 0; c < 64; c++) s += cs[c] * projW[c * 64 + tid];
    d_g[tid] = s;
}

// ---------------- MLP layer 1 (split-K) ----------------
__global__ void mlp1_main(const float* __restrict__ a, const float* __restrict__ mW1) {
    __shared__ __align__(16) float aT[64 * 36];
    __shared__ __align__(16) float Wt[64 * 132];
    int tid = threadIdx.x;
    int m0 = blockIdx.x * 32;
    int ks = blockIdx.y * 313;
    int ke = min(N_ACT, ks + 313);
    int tj = tid & 31, tb = tid >> 5;
    int j0 = tj * 4, b0 = tb * 4;
    float acc[4][4];
#pragma unroll
    for (int p = 0; p < 4; p++)
#pragma unroll
        for (int q = 0; q < 4; q++) acc[p][q] = 0.f;

    for (int kk = ks; kk < ke; kk += 64) {
        int klen = ke - kk;
        __syncthreads();
        for (int idx = tid; idx < 2048; idx += 256) {
            int b = idx >> 6, k = idx & 63;
            aT[k * 36 + b] = (k < klen) ? a[(m0 + b) * N_ACT + kk + k] : 0.f;
        }
        for (int idx = tid; idx < 8192; idx += 256) {
            int k = idx >> 7, j = idx & 127;
            Wt[k * 132 + j] = (k < klen) ? mW1[(kk + k) * 128 + j] : 0.f;
        }
        __syncthreads();
#pragma unroll 8
        for (int k = 0; k < 64; k++) {
            float4 av = *(const float4*)&aT[k * 36 + b0];
            float4 wv = *(const float4*)&Wt[k * 132 + j0];
            acc[0][0] += av.x * wv.x; acc[0][1] += av.x * wv.y; acc[0][2] += av.x * wv.z; acc[0][3] += av.x * wv.w;
            acc[1][0] += av.y * wv.x; acc[1][1] += av.y * wv.y; acc[1][2] += av.y * wv.z; acc[1][3] += av.y * wv.w;
            acc[2][0] += av.z * wv.x; acc[2][1] += av.z * wv.y; acc[2][2] += av.z * wv.z; acc[2][3] += av.z * wv.w;
            acc[3][0] += av.w * wv.x; acc[3][1] += av.w * wv.y; acc[3][2] += av.w * wv.z; acc[3][3] += av.w * wv.w;
        }
    }
#pragma unroll
    for (int p = 0; p < 4; p++)
#pragma unroll
        for (int q = 0; q < 4; q++)
            atomicAdd(&d_y1[(m0 + b0 + p) * 128 + j0 + q], acc[p][q]);
}

__global__ void mlp1_finish(const float* __restrict__ mW1, const float* __restrict__ mb1) {
    __shared__ float gs[64];
    int tid = threadIdx.x;
    if (tid < 64) gs[tid] = d_g[tid];
    __syncthreads();
    int idx = blockIdx.x * 256 + tid;
    int j = idx & 127;
    float s = d_y1[idx] + mb1[j];
    for (int c = 0; c < 64; c++) s += gs[c] * mW1[(N_ACT + c) * 128 + j];
    d_z1[idx] = fmaxf(s, 0.f);
}

__global__ void mlp2_kernel(const float* __restrict__ mW2, const float* __restrict__ mb2) {
    __shared__ float zs[2][128];
    int tid = threadIdx.x;
    int b0 = blockIdx.x * 2;
    zs[tid >> 7][tid & 127] = d_z1[b0 * 128 + tid];
    __syncthreads();
    int lb = tid >> 7, j = tid & 127;
    float s = mb2[j];
#pragma unroll 4
    for (int k = 0; k < 128; k++) s += zs[lb][k] * mW2[k * 128 + j];
    d_z2[(b0 + lb) * 128 + j] = fmaxf(s, 0.f);
}

__global__ void mlp3_kernel(const float* __restrict__ mW3, const float* __restrict__ mb3,
                            float* __restrict__ out) {
    __shared__ float w3[128];
    int tid = threadIdx.x;
    if (tid < 128) w3[tid] = mW3[tid];
    __syncthreads();
    float s = mb3[0];
    for (int j = 0; j < 128; j++) s += d_z2[tid * 128 + j] * w3[j];
    out[tid] = s;
}

// ---------------- launcher ----------------
extern "C" void kernel_launch(void* const* d_in, const int* in_sizes, int n_in,
                              void* d_out, int out_size) {
    const float* x     = (const float*)d_in[0];
    const int*   ei    = (const int*)  d_in[1];
    const float* ea    = (const float*)d_in[2];
    const float* a     = (const float*)d_in[3];
    const float* e1W1  = (const float*)d_in[4];
    const float* e1b1  = (const float*)d_in[5];
    const float* e1W2  = (const float*)d_in[6];
    const float* e1b2  = (const float*)d_in[7];
    const float* root1 = (const float*)d_in[8];
    const float* bias1 = (const float*)d_in[9];
    const float* e2W1  = (const float*)d_in[10];
    const float* e2b1  = (const float*)d_in[11];
    const float* e2W2  = (const float*)d_in[12];
    const float* e2b2  = (const float*)d_in[13];
    const float* root2 = (const float*)d_in[14];
    const float* bias2 = (const float*)d_in[15];
    const float* projW = (const float*)d_in[16];
    const float* projb = (const float*)d_in[17];
    const float* mW1   = (const float*)d_in[18];
    const float* mb1   = (const float*)d_in[19];
    const float* mW2   = (const float*)d_in[20];
    const float* mb2   = (const float*)d_in[21];
    const float* mW3   = (const float*)d_in[22];
    const float* mb3   = (const float*)d_in[23];
    float* out = (float*)d_out;

    const int s8  = (NT * (8  + 1) + 4096 + 9216 + 1088 + 544) * 4 + (TCAP + NT + 1) * 4;
    const int s64 = (NT * (64 + 1) + 4096 + 9216 + 1088 + 544) * 4 + (TCAP + NT + 1) * 4;
    cudaFuncSetAttribute(nnconv_kernel<8>,  cudaFuncAttributeMaxDynamicSharedMemorySize, s8);
    cudaFuncSetAttribute(nnconv_kernel<64>, cudaFuncAttributeMaxDynamicSharedMemorySize, s64);

    const int NB = (N_NODES + NT - 1) / NT;   // 1250

    zero_kernel<<<512, 256>>>();
    edge_feat_kernel<<<(N_EDGES + 3) / 4, 256>>>(ea, ei, e1W1, e1b1, e2W1, e2b1);
    scan_kernel<<<1, 512>>>();
    scatter_kernel<<<(N_EDGES + 255) / 256, 256>>>(ei);
    nnconv_kernel<8><<<NB, 256, s8>>>(x, e1W2, e1b2, ei);
    node_update1<<<(N_NODES + 3) / 4, 256>>>(x, root1, bias1);
    nnconv_kernel<64><<<NB, 256, s64>>>(x, e2W2, e2b2, ei);
    node_update2<<<(N_NODES + 63) / 64, 256>>>(root2, bias2);
    g_kernel<<<1, 64>>>(projW, projb);
    mlp1_main<<<dim3(8, 64), 256>>>(a, mW1);
    mlp1_finish<<<128, 256>>>(mW1, mb1);
    mlp2_kernel<<<128, 256>>>(mW2, mb2);
    mlp3_kernel<<<1, 256>>>(mW3, mb3, out);
}

// round 5
// speedup vs baseline: 1.3201x; 1.3201x over previous
#include <cuda_runtime.h>

#define N_NODES 20000
#define N_EDGES 60000
#define NODE_IN 8
#define HID     64
#define BATCH   256
#define MLP_H   128
#define N_ACT   20000

#define NT   32      // nodes per block in nnconv
#define TCAP 512     // edge-task list capacity per block

// ---------------- device scratch ----------------
__device__ float d_h1e[N_EDGES * HID];
__device__ float d_h2e[N_EDGES * HID];
__device__ float d_deg[N_NODES];
__device__ float d_agg1[N_NODES * HID];
__device__ float d_h1[N_NODES * HID];
__device__ float d_agg2[N_NODES * HID];
__device__ float d_colsum[HID];
__device__ float d_g[HID];
__device__ float d_y1[BATCH * MLP_H];
__device__ float d_z1[BATCH * MLP_H];
__device__ float d_z2[BATCH * MLP_H];
// CSR by src
__device__ int d_srccnt[N_NODES];
__device__ int d_fill[N_NODES];
__device__ int d_srcptr[N_NODES + 1];
__device__ int d_elist[N_EDGES];

// f32x2 packed helpers
__device__ __forceinline__ unsigned long long pack2(float v) {
    unsigned long long r;
    asm("mov.b64 %0, {%1, %1};" : "=l"(r) : "f"(v));
    return r;
}
__device__ __forceinline__ void fma2(unsigned long long& acc, unsigned long long a,
                                     unsigned long long b) {
    asm("fma.rn.f32x2 %0, %1, %2, %0;" : "+l"(acc) : "l"(a), "l"(b));
}

// ---------------- zero scratch ----------------
__global__ void zero_kernel() {
    int i  = blockIdx.x * blockDim.x + threadIdx.x;
    int gs = gridDim.x * blockDim.x;
    for (int j = i; j < N_NODES * HID; j += gs) { d_agg1[j] = 0.f; d_agg2[j] = 0.f; }
    for (int j = i; j < N_NODES; j += gs) { d_deg[j] = 0.f; d_srccnt[j] = 0; d_fill[j] = 0; }
    for (int j = i; j < BATCH * MLP_H; j += gs) d_y1[j] = 0.f;
    if (i < HID) d_colsum[i] = 0.f;
}

// ---------------- edge feature MLPs + degree counts ----------------
__global__ void edge_feat_kernel(const float* __restrict__ edge_attr,
                                 const int*   __restrict__ edge_index,
                                 const float* __restrict__ W1a, const float* __restrict__ b1a,
                                 const float* __restrict__ W1b, const float* __restrict__ b1b) {
    __shared__ float wa[256], wb[256], ba[64], bb[64], ea[16][4];
    int tid = threadIdx.x;
    wa[tid] = W1a[tid];
    wb[tid] = W1b[tid];
    if (tid < 64) { ba[tid] = b1a[tid]; bb[tid] = b1b[tid]; }
    int e0 = blockIdx.x * 16;
    if (tid < 64) {
        int le = tid >> 2, j = tid & 3;
        int e = e0 + le;
        ea[le][j] = (e < N_EDGES) ? edge_attr[e * 4 + j] : 0.f;
    }
    __syncthreads();
    int c = tid & 63;
#pragma unroll
    for (int ch = 0; ch < 4; ch++) {
        int le = (tid >> 6) + ch * 4;
        int e = e0 + le;
        if (e < N_EDGES) {
            float s1 = ba[c], s2 = bb[c];
#pragma unroll
            for (int j = 0; j < 4; j++) {
                s1 += ea[le][j] * wa[j * 64 + c];
                s2 += ea[le][j] * wb[j * 64 + c];
            }
            d_h1e[e * 64 + c] = fmaxf(s1, 0.f);
            d_h2e[e * 64 + c] = fmaxf(s2, 0.f);
            if (c == 0) atomicAdd(&d_deg[edge_index[N_EDGES + e]], 1.f);
            if (c == 1) atomicAdd(&d_srccnt[edge_index[e]], 1);
        }
    }
}

// ---------------- exclusive scan of src counts (single block) ----------------
__global__ void scan_kernel() {
    __shared__ int part[512];
    int tid = threadIdx.x;
    const int CH = (N_NODES + 511) / 512;   // 40
    int base = tid * CH;
    int s = 0;
    for (int j = 0; j < CH; j++) {
        int idx = base + j;
        if (idx < N_NODES) s += d_srccnt[idx];
    }
    part[tid] = s;
    __syncthreads();
    for (int off = 1; off < 512; off <<= 1) {
        int v = (tid >= off) ? part[tid - off] : 0;
        __syncthreads();
        part[tid] += v;
        __syncthreads();
    }
    int run = (tid > 0) ? part[tid - 1] : 0;
    for (int j = 0; j < CH; j++) {
        int idx = base + j;
        if (idx < N_NODES) { d_srcptr[idx] = run; run += d_srccnt[idx]; }
    }
    if (tid == 511) d_srcptr[N_NODES] = run;
}

// ---------------- scatter edges into CSR lists ----------------
__global__ void scatter_kernel(const int* __restrict__ edge_index) {
    int e = blockIdx.x * 256 + threadIdx.x;
    if (e < N_EDGES) {
        int s = edge_index[e];
        int pos = d_srcptr[s] + atomicAdd(&d_fill[s], 1);
        d_elist[pos] = e;
    }
}

// ---------------- NNConv: per-NODE weight GEMM (f32x2) fused with edge consumption ----
// Mn[n,k,o] = sum_i xin[n,i]*W2[k, i*64+o]   (register tiles, o-chunked by 8)
// msg[e,o]  = sum_k hE[e,k]*Mn[src_e,k,o] + (x[src_e]@b2)[o]  -> atomic into agg[dst]
template<int IDIM>
__launch_bounds__(256, 2)
__global__ void nnconv_kernel(const float* __restrict__ xin_param,
                              const float* __restrict__ W2,
                              const float* __restrict__ b2,
                              const int*   __restrict__ edge_index) {
    const float* xin = (IDIM == 8) ? xin_param : d_h1;
    const float* hE  = (IDIM == 8) ? d_h1e : d_h2e;
    float*       agg = (IDIM == 8) ? d_agg1 : d_agg2;
    const int*   srcp = edge_index;
    const int*   dstp = edge_index + N_EDGES;

    constexpr int WROW  = IDIM * 64;
    constexpr int XR    = 36;        // xsT row (32 nodes + pad, 16B aligned)
    constexpr int MNSTR = 522;       // per-node stride in Mns (even for STS.64, de-conflicted)

    extern __shared__ float sm[];
    float* xsT  = sm;                        // [IDIM][XR]   xsT[i][n]
    float* Wss  = xsT + IDIM * XR;           // [4096] : [8i][64k][8o]  (also b2 staging)
    float* Mns  = Wss + 4096;                // [NT][64k][8o] stride MNSTR per node
    float* bn   = Mns + NT * MNSTR;          // [NT][65]
    float* hEs  = bn + NT * 65;              // [8 warps][136] (2 halves of 68)
    int*   tasks = (int*)(hEs + 8 * 136);    // [TCAP]
    int*   sNT   = tasks + TCAP;             // [2]: ntask, csr0

    int tid = threadIdx.x;
    int nb0 = blockIdx.x * NT;

    // transposed node features (coalesced gmem read)
    for (int idx = tid; idx < NT * IDIM; idx += 256) {
        int i = idx % IDIM, n = idx / IDIM;
        int gn = nb0 + n;
        xsT[i * XR + n] = (gn < N_NODES) ? xin[gn * IDIM + i] : 0.f;
    }
    if (tid == 0) {
        int c0 = d_srcptr[nb0];
        int hi = nb0 + NT; if (hi > N_NODES) hi = N_NODES;
        sNT[0] = d_srcptr[hi] - c0;
        sNT[1] = c0;
    }
    // stage b2 into Wss
    for (int idx = tid; idx < IDIM * 64; idx += 256) Wss[idx] = b2[idx];
    __syncthreads();
    int ntask = sNT[0];
    int csr0  = sNT[1];
    // task list: ln recovered from src
    for (int t = tid; t < ntask && t < TCAP; t += 256) {
        int e = d_elist[csr0 + t];
        tasks[t] = ((srcp[e] - nb0) << 24) | e;
    }
    // bn[n][o] = sum_i xsT[i][n] * b2[i*64+o]
    for (int idx = tid; idx < NT * 64; idx += 256) {
        int o = idx & 63, n = idx >> 6;
        float s = 0.f;
#pragma unroll 8
        for (int i = 0; i < IDIM; i++) s += xsT[i * XR + n] * Wss[i * 64 + o];
        bn[n * 65 + o] = s;
    }

    int k = tid >> 2, q = tid & 3;       // GEMM role: k-row, node-quad (nodes q*8..q*8+7)
    int w = tid >> 5, l = tid & 31;      // consume role

    for (int oc = 0; oc < 8; oc++) {
        int o0 = oc * 8;
        unsigned long long acc[8][4];
#pragma unroll
        for (int a = 0; a < 8; a++)
#pragma unroll
            for (int p = 0; p < 4; p++) acc[a][p] = 0ull;

        for (int is = 0; is < IDIM / 8; is++) {
            __syncthreads();   // Wss safe to overwrite (also gates Mns overwrite vs prior consume)
            for (int idx = tid; idx < 4096; idx += 256) {
                int o = idx & 7, kk = (idx >> 3) & 63, i2 = idx >> 9;
                Wss[idx] = W2[kk * WROW + (is * 8 + i2) * 64 + o0 + o];
            }
            __syncthreads();
#pragma unroll
            for (int ii = 0; ii < 8; ii++) {
                int i = is * 8 + ii;
                const float4* xr = (const float4*)(xsT + i * XR + q * 8);
                float4 xa = xr[0], xb = xr[1];
                unsigned long long h[8];
                h[0] = pack2(xa.x); h[1] = pack2(xa.y); h[2] = pack2(xa.z); h[3] = pack2(xa.w);
                h[4] = pack2(xb.x); h[5] = pack2(xb.y); h[6] = pack2(xb.z); h[7] = pack2(xb.w);
                const unsigned long long* wp =
                    (const unsigned long long*)(Wss + (ii * 64 + k) * 8);
#pragma unroll
                for (int p = 0; p < 4; p++) {
                    unsigned long long wv = wp[p];
                    fma2(acc[0][p], h[0], wv); fma2(acc[1][p], h[1], wv);
                    fma2(acc[2][p], h[2], wv); fma2(acc[3][p], h[3], wv);
                    fma2(acc[4][p], h[4], wv); fma2(acc[5][p], h[5], wv);
                    fma2(acc[6][p], h[6], wv); fma2(acc[7][p], h[7], wv);
                }
            }
        }
        // store Mn chunk: Mns[n][k][o0..o0+7]
#pragma unroll
        for (int a = 0; a < 8; a++) {
            int n = q * 8 + a;
            unsigned long long* mp = (unsigned long long*)(Mns + n * MNSTR + k * 8);
#pragma unroll
            for (int p = 0; p < 4; p++) mp[p] = acc[a][p];
        }
        __syncthreads();

        // edge consumption: 2 tasks per warp (16 lanes each)
        float* hwbase = hEs + w * 136;
        for (int t = w * 2; t < ntask; t += 16) {
            int half = l >> 4, li = l & 15;
            int t0 = t + half;
            bool v = t0 < ntask;
            int e = 0, ln = 0;
            if (v) {
                if (t0 < TCAP) { int pk = tasks[t0]; ln = pk >> 24; e = pk & 0xFFFFFF; }
                else           { e = d_elist[csr0 + t0]; ln = srcp[e] - nb0; }
            }
            float* hw = hwbase + half * 68;
            if (v) {
                const float* hp = hE + e * 64;
                hw[li]      = hp[li];
                hw[li + 16] = hp[li + 16];
                hw[li + 32] = hp[li + 32];
                hw[li + 48] = hp[li + 48];
            }
            __syncwarp();
            int o = li & 7, kp = li >> 3;
            const float* mp = Mns + ln * MNSTR + kp * 32 * 8 + o;
            const float* hp = hw + kp * 32;
            float s = 0.f;
#pragma unroll
            for (int j = 0; j < 32; j++) s += hp[j] * mp[j * 8];
            s += __shfl_xor_sync(0xFFFFFFFFu, s, 8);
            if (v && kp == 0) {
                int d = dstp[e];
                atomicAdd(&agg[d * 64 + o0 + o], s + bn[ln * 65 + o0 + o]);
            }
            __syncwarp();
        }
        __syncthreads();
    }
}

// ---------------- node update 1 ----------------
__global__ void node_update1(const float* __restrict__ x,
                             const float* __restrict__ root1,
                             const float* __restrict__ bias1) {
    __shared__ float r1[512], b1s[64], xs[4][8], dn[4];
    int tid = threadIdx.x;
    r1[tid] = root1[tid];
    r1[tid + 256] = root1[tid + 256];
    if (tid < 64) b1s[tid] = bias1[tid];
    int n0 = blockIdx.x * 4;
    if (tid < 32) {
        int ln = tid >> 3, j = tid & 7;
        int n = n0 + ln;
        xs[ln][j] = (n < N_NODES) ? x[n * 8 + j] : 0.f;
    }
    if (tid < 4) {
        int n = n0 + tid;
        dn[tid] = (n < N_NODES) ? fmaxf(d_deg[n], 1.f) : 1.f;
    }
    __syncthreads();
    int c = tid & 63, ln = tid >> 6, n = n0 + ln;
    if (n < N_NODES) {
        float s = d_agg1[n * 64 + c] / dn[ln] + b1s[c];
#pragma unroll
        for (int j = 0; j < 8; j++) s += xs[ln][j] * r1[j * 64 + c];
        d_h1[n * 64 + c] = fmaxf(s, 0.f);
    }
}

// ---------------- node update 2 + column sums for mean pool ----------------
__global__ void node_update2(const float* __restrict__ root2,
                             const float* __restrict__ bias2) {
    __shared__ float h1s[64 * 65];
    __shared__ float r2s[64 * 64];
    __shared__ float b2s[64];
    __shared__ float dn[64];
    __shared__ float colpart[4 * 64];
    int tid = threadIdx.x;
    int n0 = blockIdx.x * 64;
    for (int idx = tid; idx < 64 * 64; idx += 256) r2s[idx] = root2[idx];
    for (int idx = tid; idx < 64 * 64; idx += 256) {
        int ln = idx >> 6, kk = idx & 63;
        int n = n0 + ln;
        h1s[ln * 65 + kk] = (n < N_NODES) ? d_h1[n * 64 + kk] : 0.f;
    }
    if (tid < 64) {
        b2s[tid] = bias2[tid];
        int n = n0 + tid;
        dn[tid] = (n < N_NODES) ? fmaxf(d_deg[n], 1.f) : 1.f;
    }
    __syncthreads();
    int c = tid & 63, ng = tid >> 6;
    float csum = 0.f;
    for (int j = 0; j < 16; j++) {
        int ln = ng + 4 * j;
        int n = n0 + ln;
        if (n < N_NODES) {
            float s = d_agg2[n * 64 + c] / dn[ln] + b2s[c];
#pragma unroll 8
            for (int kk = 0; kk < 64; kk++) s += h1s[ln * 65 + kk] * r2s[kk * 64 + c];
            csum += fmaxf(s, 0.f);
        }
    }
    colpart[ng * 64 + c] = csum;
    __syncthreads();
    if (tid < 64) {
        float t = colpart[tid] + colpart[64 + tid] + colpart[128 + tid] + colpart[192 + tid];
        atomicAdd(&d_colsum[tid], t);
    }
}

// ---------------- g vector ----------------
__global__ void g_kernel(const float* __restrict__ projW, const float* __restrict__ projb) {
    __shared__ float cs[64];
    int tid = threadIdx.x;
    cs[tid] = d_colsum[tid] * (1.f / (float)N_NODES);
    __syncthreads();
    float s = projb[tid];
    for (int c = 0; c < 64; c++) s += cs[c] * projW[c * 64 + tid];
    d_g[tid] = s;
}

// ---------------- MLP layer 1 (split-K) ----------------
__global__ void mlp1_main(const float* __restrict__ a, const float* __restrict__ mW1) {
    __shared__ __align__(16) float aT[64 * 36];
    __shared__ __align__(16) float Wt[64 * 132];
    int tid = threadIdx.x;
    int m0 = blockIdx.x * 32;
    int ks = blockIdx.y * 313;
    int ke = min(N_ACT, ks + 313);
    int tj = tid & 31, tb = tid >> 5;
    int j0 = tj * 4, b0 = tb * 4;
    float acc[4][4];
#pragma unroll
    for (int p = 0; p < 4; p++)
#pragma unroll
        for (int q = 0; q < 4; q++) acc[p][q] = 0.f;

    for (int kk = ks; kk < ke; kk += 64) {
        int klen = ke - kk;
        __syncthreads();
        for (int idx = tid; idx < 2048; idx += 256) {
            int b = idx >> 6, k = idx & 63;
            aT[k * 36 + b] = (k < klen) ? a[(m0 + b) * N_ACT + kk + k] : 0.f;
        }
        for (int idx = tid; idx < 8192; idx += 256) {
            int k = idx >> 7, j = idx & 127;
            Wt[k * 132 + j] = (k < klen) ? mW1[(kk + k) * 128 + j] : 0.f;
        }
        __syncthreads();
#pragma unroll 8
        for (int k = 0; k < 64; k++) {
            float4 av = *(const float4*)&aT[k * 36 + b0];
            float4 wv = *(const float4*)&Wt[k * 132 + j0];
            acc[0][0] += av.x * wv.x; acc[0][1] += av.x * wv.y; acc[0][2] += av.x * wv.z; acc[0][3] += av.x * wv.w;
            acc[1][0] += av.y * wv.x; acc[1][1] += av.y * wv.y; acc[1][2] += av.y * wv.z; acc[1][3] += av.y * wv.w;
            acc[2][0] += av.z * wv.x; acc[2][1] += av.z * wv.y; acc[2][2] += av.z * wv.z; acc[2][3] += av.z * wv.w;
            acc[3][0] += av.w * wv.x; acc[3][1] += av.w * wv.y; acc[3][2] += av.w * wv.z; acc[3][3] += av.w * wv.w;
        }
    }
#pragma unroll
    for (int p = 0; p < 4; p++)
#pragma unroll
        for (int q = 0; q < 4; q++)
            atomicAdd(&d_y1[(m0 + b0 + p) * 128 + j0 + q], acc[p][q]);
}

__global__ void mlp1_finish(const float* __restrict__ mW1, const float* __restrict__ mb1) {
    __shared__ float gs[64];
    int tid = threadIdx.x;
    if (tid < 64) gs[tid] = d_g[tid];
    __syncthreads();
    int idx = blockIdx.x * 256 + tid;
    int j = idx & 127;
    float s = d_y1[idx] + mb1[j];
    for (int c = 0; c < 64; c++) s += gs[c] * mW1[(N_ACT + c) * 128 + j];
    d_z1[idx] = fmaxf(s, 0.f);
}

__global__ void mlp2_kernel(const float* __restrict__ mW2, const float* __restrict__ mb2) {
    __shared__ float zs[2][128];
    int tid = threadIdx.x;
    int b0 = blockIdx.x * 2;
    zs[tid >> 7][tid & 127] = d_z1[b0 * 128 + tid];
    __syncthreads();
    int lb = tid >> 7, j = tid & 127;
    float s = mb2[j];
#pragma unroll 4
    for (int k = 0; k < 128; k++) s += zs[lb][k] * mW2[k * 128 + j];
    d_z2[(b0 + lb) * 128 + j] = fmaxf(s, 0.f);
}

__global__ void mlp3_kernel(const float* __restrict__ mW3, const float* __restrict__ mb3,
                            float* __restrict__ out) {
    __shared__ float w3[128];
    int tid = threadIdx.x;
    if (tid < 128) w3[tid] = mW3[tid];
    __syncthreads();
    float s = mb3[0];
    for (int j = 0; j < 128; j++) s += d_z2[tid * 128 + j] * w3[j];
    out[tid] = s;
}

// ---------------- launcher ----------------
extern "C" void kernel_launch(void* const* d_in, const int* in_sizes, int n_in,
                              void* d_out, int out_size) {
    const float* x     = (const float*)d_in[0];
    const int*   ei    = (const int*)  d_in[1];
    const float* ea    = (const float*)d_in[2];
    const float* a     = (const float*)d_in[3];
    const float* e1W1  = (const float*)d_in[4];
    const float* e1b1  = (const float*)d_in[5];
    const float* e1W2  = (const float*)d_in[6];
    const float* e1b2  = (const float*)d_in[7];
    const float* root1 = (const float*)d_in[8];
    const float* bias1 = (const float*)d_in[9];
    const float* e2W1  = (const float*)d_in[10];
    const float* e2b1  = (const float*)d_in[11];
    const float* e2W2  = (const float*)d_in[12];
    const float* e2b2  = (const float*)d_in[13];
    const float* root2 = (const float*)d_in[14];
    const float* bias2 = (const float*)d_in[15];
    const float* projW = (const float*)d_in[16];
    const float* projb = (const float*)d_in[17];
    const float* mW1   = (const float*)d_in[18];
    const float* mb1   = (const float*)d_in[19];
    const float* mW2   = (const float*)d_in[20];
    const float* mb2   = (const float*)d_in[21];
    const float* mW3   = (const float*)d_in[22];
    const float* mb3   = (const float*)d_in[23];
    float* out = (float*)d_out;

    const int s8  = ((8  * 36 + 4096 + NT * 522 + NT * 65 + 8 * 136) + TCAP + 2) * 4;
    const int s64 = ((64 * 36 + 4096 + NT * 522 + NT * 65 + 8 * 136) + TCAP + 2) * 4;
    cudaFuncSetAttribute(nnconv_kernel<8>,  cudaFuncAttributeMaxDynamicSharedMemorySize, s8);
    cudaFuncSetAttribute(nnconv_kernel<64>, cudaFuncAttributeMaxDynamicSharedMemorySize, s64);

    const int NB = (N_NODES + NT - 1) / NT;   // 625

    zero_kernel<<<512, 256>>>();
    edge_feat_kernel<<<(N_EDGES + 15) / 16, 256>>>(ea, ei, e1W1, e1b1, e2W1, e2b1);
    scan_kernel<<<1, 512>>>();
    scatter_kernel<<<(N_EDGES + 255) / 256, 256>>>(ei);
    nnconv_kernel<8><<<NB, 256, s8>>>(x, e1W2, e1b2, ei);
    node_update1<<<(N_NODES + 3) / 4, 256>>>(x, root1, bias1);
    nnconv_kernel<64><<<NB, 256, s64>>>(x, e2W2, e2b2, ei);
    node_update2<<<(N_NODES + 63) / 64, 256>>>(root2, bias2);
    g_kernel<<<1, 64>>>(projW, projb);
    mlp1_main<<<dim3(8, 64), 256>>>(a, mW1);
    mlp1_finish<<<128, 256>>>(mW1, mb1);
    mlp2_kernel<<<128, 256>>>(mW2, mb2);
    mlp3_kernel<<<1, 256>>>(mW3, mb3, out);
}

// round 6
// speedup vs baseline: 1.6263x; 1.2320x over previous
#include <cuda_runtime.h>

#define N_NODES 20000
#define N_EDGES 60000
#define NODE_IN 8
#define HID     64
#define BATCH   256
#define MLP_H   128
#define N_ACT   20000

#define NT   32      // nodes per block in nnconv
#define TCAP 512     // edge-task list capacity per block

// ---------------- device scratch ----------------
__device__ float d_h1e[N_EDGES * HID];
__device__ float d_h2e[N_EDGES * HID];
__device__ float d_deg[N_NODES];
__device__ float d_agg1[N_NODES * HID];
__device__ float d_h1[N_NODES * HID];
__device__ float d_agg2[N_NODES * HID];
__device__ float d_colsum[HID];
__device__ float d_g[HID];
__device__ float d_y1[BATCH * MLP_H];
__device__ float d_z1[BATCH * MLP_H];
__device__ float d_z2[BATCH * MLP_H];
// CSR by src
__device__ int d_srccnt[N_NODES];
__device__ int d_fill[N_NODES];
__device__ int d_srcptr[N_NODES + 1];
__device__ int d_elist[N_EDGES];

// f32x2 packed helpers
__device__ __forceinline__ unsigned long long pack2(float v) {
    unsigned long long r;
    asm("mov.b64 %0, {%1, %1};" : "=l"(r) : "f"(v));
    return r;
}
__device__ __forceinline__ void fma2(unsigned long long& acc, unsigned long long a,
                                     unsigned long long b) {
    asm("fma.rn.f32x2 %0, %1, %2, %0;" : "+l"(acc) : "l"(a), "l"(b));
}
__device__ __forceinline__ void unpack2(unsigned long long v, float& lo, float& hi) {
    asm("mov.b64 {%0, %1}, %2;" : "=f"(lo), "=f"(hi) : "l"(v));
}

// ---------------- zero scratch ----------------
__global__ void zero_kernel() {
    int i  = blockIdx.x * blockDim.x + threadIdx.x;
    int gs = gridDim.x * blockDim.x;
    for (int j = i; j < N_NODES * HID; j += gs) { d_agg1[j] = 0.f; d_agg2[j] = 0.f; }
    for (int j = i; j < N_NODES; j += gs) { d_deg[j] = 0.f; d_srccnt[j] = 0; d_fill[j] = 0; }
    for (int j = i; j < BATCH * MLP_H; j += gs) d_y1[j] = 0.f;
    if (i < HID) d_colsum[i] = 0.f;
}

// ---------------- edge feature MLPs + degree counts ----------------
__global__ void edge_feat_kernel(const float* __restrict__ edge_attr,
                                 const int*   __restrict__ edge_index,
                                 const float* __restrict__ W1a, const float* __restrict__ b1a,
                                 const float* __restrict__ W1b, const float* __restrict__ b1b) {
    __shared__ float wa[256], wb[256], ba[64], bb[64], ea[16][4];
    int tid = threadIdx.x;
    wa[tid] = W1a[tid];
    wb[tid] = W1b[tid];
    if (tid < 64) { ba[tid] = b1a[tid]; bb[tid] = b1b[tid]; }
    int e0 = blockIdx.x * 16;
    if (tid < 64) {
        int le = tid >> 2, j = tid & 3;
        int e = e0 + le;
        ea[le][j] = (e < N_EDGES) ? edge_attr[e * 4 + j] : 0.f;
    }
    __syncthreads();
    int c = tid & 63;
#pragma unroll
    for (int ch = 0; ch < 4; ch++) {
        int le = (tid >> 6) + ch * 4;
        int e = e0 + le;
        if (e < N_EDGES) {
            float s1 = ba[c], s2 = bb[c];
#pragma unroll
            for (int j = 0; j < 4; j++) {
                s1 += ea[le][j] * wa[j * 64 + c];
                s2 += ea[le][j] * wb[j * 64 + c];
            }
            d_h1e[e * 64 + c] = fmaxf(s1, 0.f);
            d_h2e[e * 64 + c] = fmaxf(s2, 0.f);
            if (c == 0) atomicAdd(&d_deg[edge_index[N_EDGES + e]], 1.f);
            if (c == 1) atomicAdd(&d_srccnt[edge_index[e]], 1);
        }
    }
}

// ---------------- exclusive scan of src counts (single block) ----------------
__global__ void scan_kernel() {
    __shared__ int part[512];
    int tid = threadIdx.x;
    const int CH = (N_NODES + 511) / 512;   // 40
    int base = tid * CH;
    int s = 0;
    for (int j = 0; j < CH; j++) {
        int idx = base + j;
        if (idx < N_NODES) s += d_srccnt[idx];
    }
    part[tid] = s;
    __syncthreads();
    for (int off = 1; off < 512; off <<= 1) {
        int v = (tid >= off) ? part[tid - off] : 0;
        __syncthreads();
        part[tid] += v;
        __syncthreads();
    }
    int run = (tid > 0) ? part[tid - 1] : 0;
    for (int j = 0; j < CH; j++) {
        int idx = base + j;
        if (idx < N_NODES) { d_srcptr[idx] = run; run += d_srccnt[idx]; }
    }
    if (tid == 511) d_srcptr[N_NODES] = run;
}

// ---------------- scatter edges into CSR lists ----------------
__global__ void scatter_kernel(const int* __restrict__ edge_index) {
    int e = blockIdx.x * 256 + threadIdx.x;
    if (e < N_EDGES) {
        int s = edge_index[e];
        int pos = d_srcptr[s] + atomicAdd(&d_fill[s], 1);
        d_elist[pos] = e;
    }
}

// ---------------- NNConv: per-NODE weight GEMM (f32x2), k-chunked, fused consume ----
// Chunk kc: Mn[n, kc*8..kc*8+7, 0:64] computed in registers -> smem (conflict-free),
// then consume: each edge reads an 8-float hE slice, lane l owns outputs l, l+32,
// atomically accumulating the k-partial into agg[dst].
template<int IDIM>
__launch_bounds__(256, 2)
__global__ void nnconv_kernel(const float* __restrict__ xin_param,
                              const float* __restrict__ W2,
                              const float* __restrict__ b2,
                              const int*   __restrict__ edge_index) {
    const float* xin = (IDIM == 8) ? xin_param : d_h1;
    const float* hE  = (IDIM == 8) ? d_h1e : d_h2e;
    float*       agg = (IDIM == 8) ? d_agg1 : d_agg2;
    const int*   srcp = edge_index;
    const int*   dstp = edge_index + N_EDGES;

    constexpr int WROW = IDIM * 64;
    constexpr int XR   = 36;     // xsT row stride
    constexpr int WKS  = 514;    // Wss per-k stride (conflict-free: 514/2 mod 32 = 1)
    constexpr int MKS  = 66;     // Mns per-k stride (66/2 mod 32 = 1)
    constexpr int MNS  = 8 * MKS;  // 528 per-node

    extern __shared__ float sm[];
    float* xsT  = sm;                         // [IDIM][XR]   xsT[i][n]
    float* Wss  = xsT + IDIM * XR;            // [8k][514]    (also b2 staging, flat)
    float* Mns  = Wss + 8 * WKS;              // [NT][8k][66]
    float* bn   = Mns + NT * MNS;             // [NT][65]
    float* hEs  = bn + NT * 65;               // [8 warps][4 edges][8]
    int*  tasks = (int*)(hEs + 256);          // [TCAP]  (ln<<24)|e
    int*  taskD = tasks + TCAP;               // [TCAP]  dst
    int*  sNT   = taskD + TCAP;               // [2]: ntask, csr0

    int tid = threadIdx.x;
    int nb0 = blockIdx.x * NT;

    // transposed node features
    for (int idx = tid; idx < NT * IDIM; idx += 256) {
        int i = idx % IDIM, n = idx / IDIM;
        int gn = nb0 + n;
        xsT[i * XR + n] = (gn < N_NODES) ? xin[gn * IDIM + i] : 0.f;
    }
    if (tid == 0) {
        int c0 = d_srcptr[nb0];
        int hi = nb0 + NT; if (hi > N_NODES) hi = N_NODES;
        sNT[0] = d_srcptr[hi] - c0;
        sNT[1] = c0;
    }
    // stage b2 (flat) into Wss
    for (int idx = tid; idx < IDIM * 64; idx += 256) Wss[idx] = b2[idx];
    __syncthreads();
    int ntask = sNT[0];
    int csr0  = sNT[1];
    // task lists
    for (int t = tid; t < ntask && t < TCAP; t += 256) {
        int e = d_elist[csr0 + t];
        tasks[t] = ((srcp[e] - nb0) << 24) | e;
        taskD[t] = dstp[e];
    }
    // bn[n][o] = sum_i xsT[i][n] * b2[i*64+o]
    for (int idx = tid; idx < NT * 64; idx += 256) {
        int o = idx & 63, n = idx >> 6;
        float s = 0.f;
#pragma unroll 8
        for (int i = 0; i < IDIM; i++) s += xsT[i * XR + n] * Wss[i * 64 + o];
        bn[n * 65 + o] = s;
    }

    int q  = tid >> 6;       // node oct (warp-uniform): nodes q*8..q*8+7
    int rr = tid & 63;
    int kk = rr >> 3;        // k within chunk 0..7
    int oh = rr & 7;         // o octet
    int w = tid >> 5, l = tid & 31;
    int jj = l >> 3, kx = l & 7;    // consume: edge-in-quad, k lane

    for (int kc = 0; kc < 8; kc++) {
        // ---- GEMM: Mn[32n][k=kc*8+kk][64o] over all i ----
        unsigned long long acc[8][4];
#pragma unroll
        for (int a = 0; a < 8; a++)
#pragma unroll
            for (int p = 0; p < 4; p++) acc[a][p] = 0ull;

        for (int is = 0; is < IDIM / 8; is++) {
            __syncthreads();   // Wss reuse; also gates Mns overwrite vs prev consume
            for (int idx = tid; idx < 4096; idx += 256) {
                int o = idx & 63, ks = (idx >> 6) & 7, ii = idx >> 9;
                Wss[ks * WKS + ii * 64 + o] =
                    W2[(kc * 8 + ks) * WROW + (is * 8 + ii) * 64 + o];
            }
            __syncthreads();
#pragma unroll
            for (int ii = 0; ii < 8; ii++) {
                int i = is * 8 + ii;
                const float4* xr = (const float4*)(xsT + i * XR + q * 8);
                float4 xa = xr[0], xb = xr[1];
                unsigned long long h[8];
                h[0] = pack2(xa.x); h[1] = pack2(xa.y); h[2] = pack2(xa.z); h[3] = pack2(xa.w);
                h[4] = pack2(xb.x); h[5] = pack2(xb.y); h[6] = pack2(xb.z); h[7] = pack2(xb.w);
                const unsigned long long* wp =
                    (const unsigned long long*)(Wss + kk * WKS + ii * 64 + oh * 8);
#pragma unroll
                for (int p = 0; p < 4; p++) {
                    unsigned long long wv = wp[p];
                    fma2(acc[0][p], h[0], wv); fma2(acc[1][p], h[1], wv);
                    fma2(acc[2][p], h[2], wv); fma2(acc[3][p], h[3], wv);
                    fma2(acc[4][p], h[4], wv); fma2(acc[5][p], h[5], wv);
                    fma2(acc[6][p], h[6], wv); fma2(acc[7][p], h[7], wv);
                }
            }
        }
        // store Mn chunk (conflict-free: bank-pair = k + 4*oh)
#pragma unroll
        for (int a = 0; a < 8; a++) {
            unsigned long long* mp =
                (unsigned long long*)(Mns + (q * 8 + a) * MNS + kk * MKS + oh * 8);
#pragma unroll
            for (int p = 0; p < 4; p++) mp[p] = acc[a][p];
        }
        __syncthreads();

        // ---- consume chunk: 4 edges per warp-iteration, prefetched ----
        float* hw = hEs + w * 32;
        int hEoff = kc * 8 + kx;
        int tb = w * 4;
        int pk_n = 0, d_n = 0; float hv_n = 0.f;
        {
            int t = tb + jj;
            if (t < ntask) {
                int e;
                if (t < TCAP) { pk_n = tasks[t]; d_n = taskD[t]; e = pk_n & 0xFFFFFF; }
                else { e = d_elist[csr0 + t]; pk_n = ((srcp[e] - nb0) << 24) | e; d_n = dstp[e]; }
                hv_n = hE[e * 64 + hEoff];
            }
        }
        for (; tb < ntask; tb += 32) {
            int pk_c = pk_n, d_c = d_n; float hv_c = hv_n;
            int tnext = tb + 32 + jj;
            if (tnext < ntask) {
                int e;
                if (tnext < TCAP) { pk_n = tasks[tnext]; d_n = taskD[tnext]; e = pk_n & 0xFFFFFF; }
                else { e = d_elist[csr0 + tnext]; pk_n = ((srcp[e] - nb0) << 24) | e; d_n = dstp[e]; }
                hv_n = hE[e * 64 + hEoff];
            }
            hw[jj * 8 + kx] = hv_c;
            __syncwarp();
#pragma unroll
            for (int j2 = 0; j2 < 4; j2++) {
                if (tb + j2 >= ntask) break;
                int pkj = __shfl_sync(0xFFFFFFFFu, pk_c, j2 * 8);
                int dj  = __shfl_sync(0xFFFFFFFFu, d_c,  j2 * 8);
                int ln = pkj >> 24;
                const float* mp = Mns + ln * MNS + l;
                float s0 = 0.f, s1 = 0.f;
#pragma unroll
                for (int k2 = 0; k2 < 8; k2++) {
                    float h = hw[j2 * 8 + k2];
                    s0 += h * mp[k2 * MKS];
                    s1 += h * mp[k2 * MKS + 32];
                }
                if (kc == 0) { s0 += bn[ln * 65 + l]; s1 += bn[ln * 65 + 32 + l]; }
                atomicAdd(&agg[dj * 64 + l], s0);
                atomicAdd(&agg[dj * 64 + 32 + l], s1);
            }
            __syncwarp();
        }
        __syncthreads();
    }
}

// ---------------- node update 1 ----------------
__global__ void node_update1(const float* __restrict__ x,
                             const float* __restrict__ root1,
                             const float* __restrict__ bias1) {
    __shared__ float r1[512], b1s[64], xs[4][8], dn[4];
    int tid = threadIdx.x;
    r1[tid] = root1[tid];
    r1[tid + 256] = root1[tid + 256];
    if (tid < 64) b1s[tid] = bias1[tid];
    int n0 = blockIdx.x * 4;
    if (tid < 32) {
        int ln = tid >> 3, j = tid & 7;
        int n = n0 + ln;
        xs[ln][j] = (n < N_NODES) ? x[n * 8 + j] : 0.f;
    }
    if (tid < 4) {
        int n = n0 + tid;
        dn[tid] = (n < N_NODES) ? fmaxf(d_deg[n], 1.f) : 1.f;
    }
    __syncthreads();
    int c = tid & 63, ln = tid >> 6, n = n0 + ln;
    if (n < N_NODES) {
        float s = d_agg1[n * 64 + c] / dn[ln] + b1s[c];
#pragma unroll
        for (int j = 0; j < 8; j++) s += xs[ln][j] * r1[j * 64 + c];
        d_h1[n * 64 + c] = fmaxf(s, 0.f);
    }
}

// ---------------- node update 2 + column sums for mean pool ----------------
__global__ void node_update2(const float* __restrict__ root2,
                             const float* __restrict__ bias2) {
    __shared__ float h1s[64 * 65];
    __shared__ float r2s[64 * 64];
    __shared__ float b2s[64];
    __shared__ float dn[64];
    __shared__ float colpart[4 * 64];
    int tid = threadIdx.x;
    int n0 = blockIdx.x * 64;
    for (int idx = tid; idx < 64 * 64; idx += 256) r2s[idx] = root2[idx];
    for (int idx = tid; idx < 64 * 64; idx += 256) {
        int ln = idx >> 6, kk = idx & 63;
        int n = n0 + ln;
        h1s[ln * 65 + kk] = (n < N_NODES) ? d_h1[n * 64 + kk] : 0.f;
    }
    if (tid < 64) {
        b2s[tid] = bias2[tid];
        int n = n0 + tid;
        dn[tid] = (n < N_NODES) ? fmaxf(d_deg[n], 1.f) : 1.f;
    }
    __syncthreads();
    int c = tid & 63, ng = tid >> 6;
    float csum = 0.f;
    for (int j = 0; j < 16; j++) {
        int ln = ng + 4 * j;
        int n = n0 + ln;
        if (n < N_NODES) {
            float s = d_agg2[n * 64 + c] / dn[ln] + b2s[c];
#pragma unroll 8
            for (int kk = 0; kk < 64; kk++) s += h1s[ln * 65 + kk] * r2s[kk * 64 + c];
            csum += fmaxf(s, 0.f);
        }
    }
    colpart[ng * 64 + c] = csum;
    __syncthreads();
    if (tid < 64) {
        float t = colpart[tid] + colpart[64 + tid] + colpart[128 + tid] + colpart[192 + tid];
        atomicAdd(&d_colsum[tid], t);
    }
}

// ---------------- g vector ----------------
__global__ void g_kernel(const float* __restrict__ projW, const float* __restrict__ projb) {
    __shared__ float cs[64];
    int tid = threadIdx.x;
    cs[tid] = d_colsum[tid] * (1.f / (float)N_NODES);
    __syncthreads();
    float s = projb[tid];
    for (int c = 0; c < 64; c++) s += cs[c] * projW[c * 64 + tid];
    d_g[tid] = s;
}

// ---------------- MLP layer 1 (split-K, f32x2) ----------------
__global__ void mlp1_main(const float* __restrict__ a, const float* __restrict__ mW1) {
    __shared__ __align__(16) float aT[64 * 36];
    __shared__ __align__(16) float Wt[64 * 132];
    int tid = threadIdx.x;
    int m0 = blockIdx.x * 32;
    int ks = blockIdx.y * 313;
    int ke = min(N_ACT, ks + 313);
    int tj = tid & 31, tb = tid >> 5;
    int j0 = tj * 4, b0 = tb * 4;
    unsigned long long acc2[4][2];
#pragma unroll
    for (int p = 0; p < 4; p++) { acc2[p][0] = 0ull; acc2[p][1] = 0ull; }

    for (int kkb = ks; kkb < ke; kkb += 64) {
        int klen = ke - kkb;
        __syncthreads();
        for (int idx = tid; idx < 2048; idx += 256) {
            int b = idx >> 6, k = idx & 63;
            aT[k * 36 + b] = (k < klen) ? a[(m0 + b) * N_ACT + kkb + k] : 0.f;
        }
        for (int idx = tid; idx < 8192; idx += 256) {
            int k = idx >> 7, j = idx & 127;
            Wt[k * 132 + j] = (k < klen) ? mW1[(kkb + k) * 128 + j] : 0.f;
        }
        __syncthreads();
#pragma unroll 8
        for (int k = 0; k < 64; k++) {
            float4 av = *(const float4*)&aT[k * 36 + b0];
            const unsigned long long* wp = (const unsigned long long*)&Wt[k * 132 + j0];
            unsigned long long w0 = wp[0], w1 = wp[1];
            unsigned long long a0 = pack2(av.x), a1 = pack2(av.y);
            unsigned long long a2 = pack2(av.z), a3 = pack2(av.w);
            fma2(acc2[0][0], a0, w0); fma2(acc2[0][1], a0, w1);
            fma2(acc2[1][0], a1, w0); fma2(acc2[1][1], a1, w1);
            fma2(acc2[2][0], a2, w0); fma2(acc2[2][1], a2, w1);
            fma2(acc2[3][0], a3, w0); fma2(acc2[3][1], a3, w1);
        }
    }
#pragma unroll
    for (int p = 0; p < 4; p++) {
        float v0, v1, v2, v3;
        unpack2(acc2[p][0], v0, v1);
        unpack2(acc2[p][1], v2, v3);
        float* yp = &d_y1[(m0 + b0 + p) * 128 + j0];
        atomicAdd(yp + 0, v0);
        atomicAdd(yp + 1, v1);
        atomicAdd(yp + 2, v2);
        atomicAdd(yp + 3, v3);
    }
}

__global__ void mlp1_finish(const float* __restrict__ mW1, const float* __restrict__ mb1) {
    __shared__ float gs[64];
    int tid = threadIdx.x;
    if (tid < 64) gs[tid] = d_g[tid];
    __syncthreads();
    int idx = blockIdx.x * 256 + tid;
    int j = idx & 127;
    float s = d_y1[idx] + mb1[j];
    for (int c = 0; c < 64; c++) s += gs[c] * mW1[(N_ACT + c) * 128 + j];
    d_z1[idx] = fmaxf(s, 0.f);
}

__global__ void mlp2_kernel(const float* __restrict__ mW2, const float* __restrict__ mb2) {
    __shared__ float zs[2][128];
    int tid = threadIdx.x;
    int b0 = blockIdx.x * 2;
    zs[tid >> 7][tid & 127] = d_z1[b0 * 128 + tid];
    __syncthreads();
    int lb = tid >> 7, j = tid & 127;
    float s = mb2[j];
#pragma unroll 4
    for (int k = 0; k < 128; k++) s += zs[lb][k] * mW2[k * 128 + j];
    d_z2[(b0 + lb) * 128 + j] = fmaxf(s, 0.f);
}

__global__ void mlp3_kernel(const float* __restrict__ mW3, const float* __restrict__ mb3,
                            float* __restrict__ out) {
    __shared__ float w3[128];
    int tid = threadIdx.x;
    if (tid < 128) w3[tid] = mW3[tid];
    __syncthreads();
    float s = mb3[0];
    for (int j = 0; j < 128; j++) s += d_z2[tid * 128 + j] * w3[j];
    out[tid] = s;
}

// ---------------- launcher ----------------
extern "C" void kernel_launch(void* const* d_in, const int* in_sizes, int n_in,
                              void* d_out, int out_size) {
    const float* x     = (const float*)d_in[0];
    const int*   ei    = (const int*)  d_in[1];
    const float* ea    = (const float*)d_in[2];
    const float* a     = (const float*)d_in[3];
    const float* e1W1  = (const float*)d_in[4];
    const float* e1b1  = (const float*)d_in[5];
    const float* e1W2  = (const float*)d_in[6];
    const float* e1b2  = (const float*)d_in[7];
    const float* root1 = (const float*)d_in[8];
    const float* bias1 = (const float*)d_in[9];
    const float* e2W1  = (const float*)d_in[10];
    const float* e2b1  = (const float*)d_in[11];
    const float* e2W2  = (const float*)d_in[12];
    const float* e2b2  = (const float*)d_in[13];
    const float* root2 = (const float*)d_in[14];
    const float* bias2 = (const float*)d_in[15];
    const float* projW = (const float*)d_in[16];
    const float* projb = (const float*)d_in[17];
    const float* mW1   = (const float*)d_in[18];
    const float* mb1   = (const float*)d_in[19];
    const float* mW2   = (const float*)d_in[20];
    const float* mb2   = (const float*)d_in[21];
    const float* mW3   = (const float*)d_in[22];
    const float* mb3   = (const float*)d_in[23];
    float* out = (float*)d_out;

    // smem: xsT + Wss(8*514) + Mns(32*528) + bn(32*65) + hEs(256) + tasks + taskD + 2
    const int sbase = (8 * 514 + NT * 528 + NT * 65 + 256 + TCAP + TCAP + 2);
    const int s8  = (8  * 36 + sbase) * 4;
    const int s64 = (64 * 36 + sbase) * 4;
    cudaFuncSetAttribute(nnconv_kernel<8>,  cudaFuncAttributeMaxDynamicSharedMemorySize, s8);
    cudaFuncSetAttribute(nnconv_kernel<64>, cudaFuncAttributeMaxDynamicSharedMemorySize, s64);

    const int NB = (N_NODES + NT - 1) / NT;   // 625

    zero_kernel<<<512, 256>>>();
    edge_feat_kernel<<<(N_EDGES + 15) / 16, 256>>>(ea, ei, e1W1, e1b1, e2W1, e2b1);
    scan_kernel<<<1, 512>>>();
    scatter_kernel<<<(N_EDGES + 255) / 256, 256>>>(ei);
    nnconv_kernel<8><<<NB, 256, s8>>>(x, e1W2, e1b2, ei);
    node_update1<<<(N_NODES + 3) / 4, 256>>>(x, root1, bias1);
    nnconv_kernel<64><<<NB, 256, s64>>>(x, e2W2, e2b2, ei);
    node_update2<<<(N_NODES + 63) / 64, 256>>>(root2, bias2);
    g_kernel<<<1, 64>>>(projW, projb);
    mlp1_main<<<dim3(8, 64), 256>>>(a, mW1);
    mlp1_finish<<<128, 256>>>(mW1, mb1);
    mlp2_kernel<<<128, 256>>>(mW2, mb2);
    mlp3_kernel<<<1, 256>>>(mW3, mb3, out);
}

// round 7
// speedup vs baseline: 1.6658x; 1.0243x over previous
#include <cuda_runtime.h>

#define N_NODES 20000
#define N_EDGES 60000
#define NODE_IN 8
#define HID     64
#define BATCH   256
#define MLP_H   128
#define N_ACT   20000

#define NT    64     // nodes per block in nnconv
#define NTHR  512    // threads per nnconv block
#define TCAP  1024   // edge-task list capacity per block
#define WBUF  4112   // 8*514 floats per Wss buffer

// ---------------- device scratch ----------------
__device__ float d_h1e[N_EDGES * HID];
__device__ float d_h2e[N_EDGES * HID];
__device__ float d_deg[N_NODES];
__device__ float d_agg1[N_NODES * HID];
__device__ float d_h1[N_NODES * HID];
__device__ float d_agg2[N_NODES * HID];
__device__ float d_colsum[HID];
__device__ float d_g[HID];
__device__ float d_y1[BATCH * MLP_H];
__device__ float d_z1[BATCH * MLP_H];
__device__ float d_z2[BATCH * MLP_H];
// CSR by src
__device__ int d_srccnt[N_NODES];
__device__ int d_fill[N_NODES];
__device__ int d_srcptr[N_NODES + 1];
__device__ int d_elist[N_EDGES];

// f32x2 packed helpers
__device__ __forceinline__ unsigned long long pack2(float v) {
    unsigned long long r;
    asm("mov.b64 %0, {%1, %1};" : "=l"(r) : "f"(v));
    return r;
}
__device__ __forceinline__ void fma2(unsigned long long& acc, unsigned long long a,
                                     unsigned long long b) {
    asm("fma.rn.f32x2 %0, %1, %2, %0;" : "+l"(acc) : "l"(a), "l"(b));
}
__device__ __forceinline__ void unpack2(unsigned long long v, float& lo, float& hi) {
    asm("mov.b64 {%0, %1}, %2;" : "=f"(lo), "=f"(hi) : "l"(v));
}
// cp.async helpers
__device__ __forceinline__ void cpa8(unsigned dst, const void* src) {
    asm volatile("cp.async.ca.shared.global [%0], [%1], 8;" :: "r"(dst), "l"(src) : "memory");
}
__device__ __forceinline__ void cpa_commit() {
    asm volatile("cp.async.commit_group;" ::: "memory");
}
template<int N> __device__ __forceinline__ void cpa_wait() {
    asm volatile("cp.async.wait_group %0;" :: "n"(N) : "memory");
}

// ---------------- zero scratch ----------------
__global__ void zero_kernel() {
    int i  = blockIdx.x * blockDim.x + threadIdx.x;
    int gs = gridDim.x * blockDim.x;
    for (int j = i; j < N_NODES * HID; j += gs) { d_agg1[j] = 0.f; d_agg2[j] = 0.f; }
    for (int j = i; j < N_NODES; j += gs) { d_deg[j] = 0.f; d_srccnt[j] = 0; d_fill[j] = 0; }
    for (int j = i; j < BATCH * MLP_H; j += gs) d_y1[j] = 0.f;
    if (i < HID) d_colsum[i] = 0.f;
}

// ---------------- edge feature MLPs + degree counts ----------------
__global__ void edge_feat_kernel(const float* __restrict__ edge_attr,
                                 const int*   __restrict__ edge_index,
                                 const float* __restrict__ W1a, const float* __restrict__ b1a,
                                 const float* __restrict__ W1b, const float* __restrict__ b1b) {
    __shared__ float wa[256], wb[256], ba[64], bb[64], ea[16][4];
    int tid = threadIdx.x;
    wa[tid] = W1a[tid];
    wb[tid] = W1b[tid];
    if (tid < 64) { ba[tid] = b1a[tid]; bb[tid] = b1b[tid]; }
    int e0 = blockIdx.x * 16;
    if (tid < 64) {
        int le = tid >> 2, j = tid & 3;
        int e = e0 + le;
        ea[le][j] = (e < N_EDGES) ? edge_attr[e * 4 + j] : 0.f;
    }
    __syncthreads();
    int c = tid & 63;
#pragma unroll
    for (int ch = 0; ch < 4; ch++) {
        int le = (tid >> 6) + ch * 4;
        int e = e0 + le;
        if (e < N_EDGES) {
            float s1 = ba[c], s2 = bb[c];
#pragma unroll
            for (int j = 0; j < 4; j++) {
                s1 += ea[le][j] * wa[j * 64 + c];
                s2 += ea[le][j] * wb[j * 64 + c];
            }
            d_h1e[e * 64 + c] = fmaxf(s1, 0.f);
            d_h2e[e * 64 + c] = fmaxf(s2, 0.f);
            if (c == 0) atomicAdd(&d_deg[edge_index[N_EDGES + e]], 1.f);
            if (c == 1) atomicAdd(&d_srccnt[edge_index[e]], 1);
        }
    }
}

// ---------------- exclusive scan of src counts (single block) ----------------
__global__ void scan_kernel() {
    __shared__ int part[512];
    int tid = threadIdx.x;
    const int CH = (N_NODES + 511) / 512;   // 40
    int base = tid * CH;
    int s = 0;
    for (int j = 0; j < CH; j++) {
        int idx = base + j;
        if (idx < N_NODES) s += d_srccnt[idx];
    }
    part[tid] = s;
    __syncthreads();
    for (int off = 1; off < 512; off <<= 1) {
        int v = (tid >= off) ? part[tid - off] : 0;
        __syncthreads();
        part[tid] += v;
        __syncthreads();
    }
    int run = (tid > 0) ? part[tid - 1] : 0;
    for (int j = 0; j < CH; j++) {
        int idx = base + j;
        if (idx < N_NODES) { d_srcptr[idx] = run; run += d_srccnt[idx]; }
    }
    if (tid == 511) d_srcptr[N_NODES] = run;
}

// ---------------- scatter edges into CSR lists ----------------
__global__ void scatter_kernel(const int* __restrict__ edge_index) {
    int e = blockIdx.x * 256 + threadIdx.x;
    if (e < N_EDGES) {
        int s = edge_index[e];
        int pos = d_srcptr[s] + atomicAdd(&d_fill[s], 1);
        d_elist[pos] = e;
    }
}

// ---------------- W2 tile prefetch (cp.async, 8B) ----------------
template<int IDIM>
__device__ __forceinline__ void stage_w2(const float* __restrict__ W2,
                                         unsigned wss_smem, int kc, int is, int tid) {
    constexpr int WROW = IDIM * 64;
#pragma unroll
    for (int j = 0; j < 4; j++) {
        int p2 = tid + j * NTHR;          // pair index 0..2047
        int o2 = p2 & 31;
        int ks = (p2 >> 5) & 7;
        int ii = p2 >> 8;
        const float* src = W2 + (kc * 8 + ks) * WROW + (is * 8 + ii) * 64 + o2 * 2;
        unsigned dst = wss_smem + (unsigned)((ks * 514 + ii * 64 + o2 * 2) * 4);
        cpa8(dst, src);
    }
}

// ---------------- NNConv: per-NODE weight GEMM (f32x2), k-chunked, cp.async pipeline --
template<int IDIM>
__launch_bounds__(NTHR, 1)
__global__ void nnconv_kernel(const float* __restrict__ xin_param,
                              const float* __restrict__ W2,
                              const float* __restrict__ b2,
                              const int*   __restrict__ edge_index) {
    const float* xin = (IDIM == 8) ? xin_param : d_h1;
    const float* hE  = (IDIM == 8) ? d_h1e : d_h2e;
    float*       agg = (IDIM == 8) ? d_agg1 : d_agg2;
    const int*   srcp = edge_index;
    const int*   dstp = edge_index + N_EDGES;

    constexpr int IS   = IDIM / 8;   // i-stages per k-chunk
    constexpr int XR   = 68;         // xsT row stride (NT + pad, 16B aligned)
    constexpr int MKS  = 66;         // Mns per-k stride
    constexpr int MNS  = 8 * MKS;    // 528 per node

    extern __shared__ float sm[];
    float* xsT  = sm;                         // [IDIM][XR]   xsT[i][n]
    float* Wss  = xsT + IDIM * XR;            // [2][8][514]  double-buffered W2 tile
    float* Mns  = Wss + 2 * WBUF;             // [NT][8k][66] (first 4096 reused for b2)
    float* bn   = Mns + NT * MNS;             // [NT][65]
    float* hEs  = bn + NT * 65;               // [16 warps][32]
    int*  tasks = (int*)(hEs + 16 * 32);      // [TCAP]  (ln<<24)|e
    int*  taskD = tasks + TCAP;               // [TCAP]  dst
    int*  sNT   = taskD + TCAP;               // [2]: ntask, csr0

    int tid = threadIdx.x;
    int nb0 = blockIdx.x * NT;
    unsigned wss_base = (unsigned)__cvta_generic_to_shared(Wss);

    // kick off pipeline: stage (kc=0, is=0) into buffer 0
    stage_w2<IDIM>(W2, wss_base, 0, 0, tid);
    cpa_commit();

    // transposed node features
    for (int idx = tid; idx < NT * IDIM; idx += NTHR) {
        int i = idx % IDIM, n = idx / IDIM;
        int gn = nb0 + n;
        xsT[i * XR + n] = (gn < N_NODES) ? xin[gn * IDIM + i] : 0.f;
    }
    if (tid == 0) {
        int c0 = d_srcptr[nb0];
        int hi = nb0 + NT; if (hi > N_NODES) hi = N_NODES;
        sNT[0] = d_srcptr[hi] - c0;
        sNT[1] = c0;
    }
    // stage b2 (flat) into Mns head (free until first Mn store)
    for (int idx = tid; idx < IDIM * 64; idx += NTHR) Mns[idx] = b2[idx];
    __syncthreads();
    int ntask = sNT[0];
    int csr0  = sNT[1];
    // task lists
    for (int t = tid; t < ntask && t < TCAP; t += NTHR) {
        int e = d_elist[csr0 + t];
        tasks[t] = ((srcp[e] - nb0) << 24) | e;
        taskD[t] = dstp[e];
    }
    // bn[n][o] = sum_i xsT[i][n] * b2[i*64+o]
    for (int idx = tid; idx < NT * 64; idx += NTHR) {
        int o = idx & 63, n = idx >> 6;
        float s = 0.f;
#pragma unroll 8
        for (int i = 0; i < IDIM; i++) s += xsT[i * XR + n] * Mns[i * 64 + o];
        bn[n * 65 + o] = s;
    }

    int q  = tid >> 6;       // node oct (warp-uniform): nodes q*8..q*8+7
    int rr = tid & 63;
    int kk = rr >> 3;        // k within chunk (warp window 0..3 or 4..7)
    int oh = rr & 7;         // o octet
    int w = tid >> 5, l = tid & 31;
    int jj = l >> 3, kx = l & 7;    // consume: edge-in-quad, k lane

    int buf = 0;
    for (int kc = 0; kc < 8; kc++) {
        unsigned long long acc[8][4];
#pragma unroll
        for (int a = 0; a < 8; a++)
#pragma unroll
            for (int p = 0; p < 4; p++) acc[a][p] = 0ull;

        for (int is = 0; is < IS; is++) {
            __syncthreads();   // all readers of buf^1 (prev stage) / consume of prev kc done
            int sn = kc * IS + is + 1;
            if (sn < 8 * IS) {
                stage_w2<IDIM>(W2, wss_base + (unsigned)((buf ^ 1) * WBUF * 4),
                               sn / IS, sn % IS, tid);
                cpa_commit();
                cpa_wait<1>();   // current stage's copy complete
            } else {
                cpa_wait<0>();
            }
            __syncthreads();     // current buffer visible to all

            const float* Wc = Wss + buf * WBUF;
#pragma unroll
            for (int ii = 0; ii < 8; ii++) {
                int i = is * 8 + ii;
                const float4* xr = (const float4*)(xsT + i * XR + q * 8);
                float4 xa = xr[0], xb = xr[1];
                unsigned long long h[8];
                h[0] = pack2(xa.x); h[1] = pack2(xa.y); h[2] = pack2(xa.z); h[3] = pack2(xa.w);
                h[4] = pack2(xb.x); h[5] = pack2(xb.y); h[6] = pack2(xb.z); h[7] = pack2(xb.w);
                const unsigned long long* wp =
                    (const unsigned long long*)(Wc + kk * 514 + ii * 64 + oh * 8);
#pragma unroll
                for (int p = 0; p < 4; p++) {
                    unsigned long long wv = wp[p];
                    fma2(acc[0][p], h[0], wv); fma2(acc[1][p], h[1], wv);
                    fma2(acc[2][p], h[2], wv); fma2(acc[3][p], h[3], wv);
                    fma2(acc[4][p], h[4], wv); fma2(acc[5][p], h[5], wv);
                    fma2(acc[6][p], h[6], wv); fma2(acc[7][p], h[7], wv);
                }
            }
            buf ^= 1;
        }

        // store Mn chunk (conflict-free)
#pragma unroll
        for (int a = 0; a < 8; a++) {
            unsigned long long* mp =
                (unsigned long long*)(Mns + (q * 8 + a) * MNS + kk * MKS + oh * 8);
#pragma unroll
            for (int p = 0; p < 4; p++) mp[p] = acc[a][p];
        }
        __syncthreads();

        // ---- consume chunk: 4 edges per warp-iteration, prefetched ----
        float* hw = hEs + w * 32;
        int hEoff = kc * 8 + kx;
        int tb = w * 4;
        int pk_n = 0, d_n = 0; float hv_n = 0.f;
        {
            int t = tb + jj;
            if (t < ntask) {
                int e;
                if (t < TCAP) { pk_n = tasks[t]; d_n = taskD[t]; e = pk_n & 0xFFFFFF; }
                else { e = d_elist[csr0 + t]; pk_n = ((srcp[e] - nb0) << 24) | e; d_n = dstp[e]; }
                hv_n = hE[e * 64 + hEoff];
            }
        }
        for (; tb < ntask; tb += 64) {
            int pk_c = pk_n, d_c = d_n; float hv_c = hv_n;
            int tnext = tb + 64 + jj;
            if (tnext < ntask) {
                int e;
                if (tnext < TCAP) { pk_n = tasks[tnext]; d_n = taskD[tnext]; e = pk_n & 0xFFFFFF; }
                else { e = d_elist[csr0 + tnext]; pk_n = ((srcp[e] - nb0) << 24) | e; d_n = dstp[e]; }
                hv_n = hE[e * 64 + hEoff];
            }
            hw[jj * 8 + kx] = hv_c;
            __syncwarp();
#pragma unroll
            for (int j2 = 0; j2 < 4; j2++) {
                if (tb + j2 >= ntask) break;
                int pkj = __shfl_sync(0xFFFFFFFFu, pk_c, j2 * 8);
                int dj  = __shfl_sync(0xFFFFFFFFu, d_c,  j2 * 8);
                int ln = pkj >> 24;
                const float* mp = Mns + ln * MNS + l;
                float s0 = 0.f, s1 = 0.f;
#pragma unroll
                for (int k2 = 0; k2 < 8; k2++) {
                    float h = hw[j2 * 8 + k2];
                    s0 += h * mp[k2 * MKS];
                    s1 += h * mp[k2 * MKS + 32];
                }
                if (kc == 0) { s0 += bn[ln * 65 + l]; s1 += bn[ln * 65 + 32 + l]; }
                atomicAdd(&agg[dj * 64 + l], s0);
                atomicAdd(&agg[dj * 64 + 32 + l], s1);
            }
            __syncwarp();
        }
    }
}

// ---------------- node update 1 ----------------
__global__ void node_update1(const float* __restrict__ x,
                             const float* __restrict__ root1,
                             const float* __restrict__ bias1) {
    __shared__ float r1[512], b1s[64], xs[4][8], dn[4];
    int tid = threadIdx.x;
    r1[tid] = root1[tid];
    r1[tid + 256] = root1[tid + 256];
    if (tid < 64) b1s[tid] = bias1[tid];
    int n0 = blockIdx.x * 4;
    if (tid < 32) {
        int ln = tid >> 3, j = tid & 7;
        int n = n0 + ln;
        xs[ln][j] = (n < N_NODES) ? x[n * 8 + j] : 0.f;
    }
    if (tid < 4) {
        int n = n0 + tid;
        dn[tid] = (n < N_NODES) ? fmaxf(d_deg[n], 1.f) : 1.f;
    }
    __syncthreads();
    int c = tid & 63, ln = tid >> 6, n = n0 + ln;
    if (n < N_NODES) {
        float s = d_agg1[n * 64 + c] / dn[ln] + b1s[c];
#pragma unroll
        for (int j = 0; j < 8; j++) s += xs[ln][j] * r1[j * 64 + c];
        d_h1[n * 64 + c] = fmaxf(s, 0.f);
    }
}

// ---------------- node update 2 + column sums for mean pool ----------------
__global__ void node_update2(const float* __restrict__ root2,
                             const float* __restrict__ bias2) {
    __shared__ float h1s[64 * 65];
    __shared__ float r2s[64 * 64];
    __shared__ float b2s[64];
    __shared__ float dn[64];
    __shared__ float colpart[4 * 64];
    int tid = threadIdx.x;
    int n0 = blockIdx.x * 64;
    for (int idx = tid; idx < 64 * 64; idx += 256) r2s[idx] = root2[idx];
    for (int idx = tid; idx < 64 * 64; idx += 256) {
        int ln = idx >> 6, kk = idx & 63;
        int n = n0 + ln;
        h1s[ln * 65 + kk] = (n < N_NODES) ? d_h1[n * 64 + kk] : 0.f;
    }
    if (tid < 64) {
        b2s[tid] = bias2[tid];
        int n = n0 + tid;
        dn[tid] = (n < N_NODES) ? fmaxf(d_deg[n], 1.f) : 1.f;
    }
    __syncthreads();
    int c = tid & 63, ng = tid >> 6;
    float csum = 0.f;
    for (int j = 0; j < 16; j++) {
        int ln = ng + 4 * j;
        int n = n0 + ln;
        if (n < N_NODES) {
            float s = d_agg2[n * 64 + c] / dn[ln] + b2s[c];
#pragma unroll 8
            for (int kk = 0; kk < 64; kk++) s += h1s[ln * 65 + kk] * r2s[kk * 64 + c];
            csum += fmaxf(s, 0.f);
        }
    }
    colpart[ng * 64 + c] = csum;
    __syncthreads();
    if (tid < 64) {
        float t = colpart[tid] + colpart[64 + tid] + colpart[128 + tid] + colpart[192 + tid];
        atomicAdd(&d_colsum[tid], t);
    }
}

// ---------------- g vector ----------------
__global__ void g_kernel(const float* __restrict__ projW, const float* __restrict__ projb) {
    __shared__ float cs[64];
    int tid = threadIdx.x;
    cs[tid] = d_colsum[tid] * (1.f / (float)N_NODES);
    __syncthreads();
    float s = projb[tid];
    for (int c = 0; c < 64; c++) s += cs[c] * projW[c * 64 + tid];
    d_g[tid] = s;
}

// ---------------- MLP layer 1 (split-K, f32x2) ----------------
__global__ void mlp1_main(const float* __restrict__ a, const float* __restrict__ mW1) {
    __shared__ __align__(16) float aT[64 * 36];
    __shared__ __align__(16) float Wt[64 * 132];
    int tid = threadIdx.x;
    int m0 = blockIdx.x * 32;
    int ks = blockIdx.y * 313;
    int ke = min(N_ACT, ks + 313);
    int tj = tid & 31, tb = tid >> 5;
    int j0 = tj * 4, b0 = tb * 4;
    unsigned long long acc2[4][2];
#pragma unroll
    for (int p = 0; p < 4; p++) { acc2[p][0] = 0ull; acc2[p][1] = 0ull; }

    for (int kkb = ks; kkb < ke; kkb += 64) {
        int klen = ke - kkb;
        __syncthreads();
        for (int idx = tid; idx < 2048; idx += 256) {
            int b = idx >> 6, k = idx & 63;
            aT[k * 36 + b] = (k < klen) ? a[(m0 + b) * N_ACT + kkb + k] : 0.f;
        }
        for (int idx = tid; idx < 8192; idx += 256) {
            int k = idx >> 7, j = idx & 127;
            Wt[k * 132 + j] = (k < klen) ? mW1[(kkb + k) * 128 + j] : 0.f;
        }
        __syncthreads();
#pragma unroll 8
        for (int k = 0; k < 64; k++) {
            float4 av = *(const float4*)&aT[k * 36 + b0];
            const unsigned long long* wp = (const unsigned long long*)&Wt[k * 132 + j0];
            unsigned long long w0 = wp[0], w1 = wp[1];
            unsigned long long a0 = pack2(av.x), a1 = pack2(av.y);
            unsigned long long a2 = pack2(av.z), a3 = pack2(av.w);
            fma2(acc2[0][0], a0, w0); fma2(acc2[0][1], a0, w1);
            fma2(acc2[1][0], a1, w0); fma2(acc2[1][1], a1, w1);
            fma2(acc2[2][0], a2, w0); fma2(acc2[2][1], a2, w1);
            fma2(acc2[3][0], a3, w0); fma2(acc2[3][1], a3, w1);
        }
    }
#pragma unroll
    for (int p = 0; p < 4; p++) {
        float v0, v1, v2, v3;
        unpack2(acc2[p][0], v0, v1);
        unpack2(acc2[p][1], v2, v3);
        float* yp = &d_y1[(m0 + b0 + p) * 128 + j0];
        atomicAdd(yp + 0, v0);
        atomicAdd(yp + 1, v1);
        atomicAdd(yp + 2, v2);
        atomicAdd(yp + 3, v3);
    }
}

__global__ void mlp1_finish(const float* __restrict__ mW1, const float* __restrict__ mb1) {
    __shared__ float gs[64];
    int tid = threadIdx.x;
    if (tid < 64) gs[tid] = d_g[tid];
    __syncthreads();
    int idx = blockIdx.x * 256 + tid;
    int j = idx & 127;
    float s = d_y1[idx] + mb1[j];
    for (int c = 0; c < 64; c++) s += gs[c] * mW1[(N_ACT + c) * 128 + j];
    d_z1[idx] = fmaxf(s, 0.f);
}

__global__ void mlp2_kernel(const float* __restrict__ mW2, const float* __restrict__ mb2) {
    __shared__ float zs[2][128];
    int tid = threadIdx.x;
    int b0 = blockIdx.x * 2;
    zs[tid >> 7][tid & 127] = d_z1[b0 * 128 + tid];
    __syncthreads();
    int lb = tid >> 7, j = tid & 127;
    float s = mb2[j];
#pragma unroll 4
    for (int k = 0; k < 128; k++) s += zs[lb][k] * mW2[k * 128 + j];
    d_z2[(b0 + lb) * 128 + j] = fmaxf(s, 0.f);
}

__global__ void mlp3_kernel(const float* __restrict__ mW3, const float* __restrict__ mb3,
                            float* __restrict__ out) {
    __shared__ float w3[128];
    int tid = threadIdx.x;
    if (tid < 128) w3[tid] = mW3[tid];
    __syncthreads();
    float s = mb3[0];
    for (int j = 0; j < 128; j++) s += d_z2[tid * 128 + j] * w3[j];
    out[tid] = s;
}

// ---------------- launcher ----------------
extern "C" void kernel_launch(void* const* d_in, const int* in_sizes, int n_in,
                              void* d_out, int out_size) {
    const float* x     = (const float*)d_in[0];
    const int*   ei    = (const int*)  d_in[1];
    const float* ea    = (const float*)d_in[2];
    const float* a     = (const float*)d_in[3];
    const float* e1W1  = (const float*)d_in[4];
    const float* e1b1  = (const float*)d_in[5];
    const float* e1W2  = (const float*)d_in[6];
    const float* e1b2  = (const float*)d_in[7];
    const float* root1 = (const float*)d_in[8];
    const float* bias1 = (const float*)d_in[9];
    const float* e2W1  = (const float*)d_in[10];
    const float* e2b1  = (const float*)d_in[11];
    const float* e2W2  = (const float*)d_in[12];
    const float* e2b2  = (const float*)d_in[13];
    const float* root2 = (const float*)d_in[14];
    const float* bias2 = (const float*)d_in[15];
    const float* projW = (const float*)d_in[16];
    const float* projb = (const float*)d_in[17];
    const float* mW1   = (const float*)d_in[18];
    const float* mb1   = (const float*)d_in[19];
    const float* mW2   = (const float*)d_in[20];
    const float* mb2   = (const float*)d_in[21];
    const float* mW3   = (const float*)d_in[22];
    const float* mb3   = (const float*)d_in[23];
    float* out = (float*)d_out;

    // smem: xsT + Wss(2*4112) + Mns(64*528) + bn(64*65) + hEs(512) + tasks + taskD + 2
    const int sbase = (2 * WBUF + NT * 528 + NT * 65 + 512 + TCAP + TCAP + 2);
    const int s8  = (8  * 68 + sbase) * 4;
    const int s64 = (64 * 68 + sbase) * 4;
    cudaFuncSetAttribute(nnconv_kernel<8>,  cudaFuncAttributeMaxDynamicSharedMemorySize, s8);
    cudaFuncSetAttribute(nnconv_kernel<64>, cudaFuncAttributeMaxDynamicSharedMemorySize, s64);

    const int NB = (N_NODES + NT - 1) / NT;   // 313

    zero_kernel<<<512, 256>>>();
    edge_feat_kernel<<<(N_EDGES + 15) / 16, 256>>>(ea, ei, e1W1, e1b1, e2W1, e2b1);
    scan_kernel<<<1, 512>>>();
    scatter_kernel<<<(N_EDGES + 255) / 256, 256>>>(ei);
    nnconv_kernel<8><<<NB, NTHR, s8>>>(x, e1W2, e1b2, ei);
    node_update1<<<(N_NODES + 3) / 4, 256>>>(x, root1, bias1);
    nnconv_kernel<64><<<NB, NTHR, s64>>>(x, e2W2, e2b2, ei);
    node_update2<<<(N_NODES + 63) / 64, 256>>>(root2, bias2);
    g_kernel<<<1, 64>>>(projW, projb);
    mlp1_main<<<dim3(8, 64), 256>>>(a, mW1);
    mlp1_finish<<<128, 256>>>(mW1, mb1);
    mlp2_kernel<<<128, 256>>>(mW2, mb2);
    mlp3_kernel<<<1, 256>>>(mW3, mb3, out);
}

// round 8
// speedup vs baseline: 1.7171x; 1.0308x over previous
#include <cuda_runtime.h>

#define N_NODES 20000
#define N_EDGES 60000
#define NODE_IN 8
#define HID     64
#define BATCH   256
#define MLP_H   128
#define N_ACT   20000

#define NT    32     // nodes per block in nnconv
#define NTHR  256    // threads per nnconv block
#define TCAP  256    // edge-task list capacity per block
#define TMAXW 14     // register msg-accumulator slots per warp (covers 112 tasks/block)
#define WBUF  4112   // 8*514 floats in the Wss buffer

// ---------------- device scratch ----------------
__device__ float d_h1e[N_EDGES * HID];
__device__ float d_h2e[N_EDGES * HID];
__device__ float d_deg[N_NODES];
__device__ float d_agg1[N_NODES * HID];
__device__ float d_h1[N_NODES * HID];
__device__ float d_agg2[N_NODES * HID];
__device__ float d_colsum[HID];
__device__ float d_g[HID];
__device__ float d_y1[BATCH * MLP_H];
__device__ float d_z1[BATCH * MLP_H];
__device__ float d_z2[BATCH * MLP_H];
// CSR by src
__device__ int d_srccnt[N_NODES];
__device__ int d_fill[N_NODES];
__device__ int d_srcptr[N_NODES + 1];
__device__ int d_elist[N_EDGES];

// f32x2 packed helpers
__device__ __forceinline__ unsigned long long pack2(float v) {
    unsigned long long r;
    asm("mov.b64 %0, {%1, %1};" : "=l"(r) : "f"(v));
    return r;
}
__device__ __forceinline__ void fma2(unsigned long long& acc, unsigned long long a,
                                     unsigned long long b) {
    asm("fma.rn.f32x2 %0, %1, %2, %0;" : "+l"(acc) : "l"(a), "l"(b));
}
__device__ __forceinline__ void unpack2(unsigned long long v, float& lo, float& hi) {
    asm("mov.b64 {%0, %1}, %2;" : "=f"(lo), "=f"(hi) : "l"(v));
}
// cp.async helpers
__device__ __forceinline__ void cpa8(unsigned dst, const void* src) {
    asm volatile("cp.async.ca.shared.global [%0], [%1], 8;" :: "r"(dst), "l"(src) : "memory");
}
__device__ __forceinline__ void cpa_commit() {
    asm volatile("cp.async.commit_group;" ::: "memory");
}
template<int N> __device__ __forceinline__ void cpa_wait() {
    asm volatile("cp.async.wait_group %0;" :: "n"(N) : "memory");
}

// ---------------- zero scratch ----------------
__global__ void zero_kernel() {
    int i  = blockIdx.x * blockDim.x + threadIdx.x;
    int gs = gridDim.x * blockDim.x;
    for (int j = i; j < N_NODES * HID; j += gs) { d_agg1[j] = 0.f; d_agg2[j] = 0.f; }
    for (int j = i; j < N_NODES; j += gs) { d_deg[j] = 0.f; d_srccnt[j] = 0; d_fill[j] = 0; }
    for (int j = i; j < BATCH * MLP_H; j += gs) d_y1[j] = 0.f;
    if (i < HID) d_colsum[i] = 0.f;
}

// ---------------- edge feature MLPs + degree counts ----------------
__global__ void edge_feat_kernel(const float* __restrict__ edge_attr,
                                 const int*   __restrict__ edge_index,
                                 const float* __restrict__ W1a, const float* __restrict__ b1a,
                                 const float* __restrict__ W1b, const float* __restrict__ b1b) {
    __shared__ float wa[256], wb[256], ba[64], bb[64], ea[16][4];
    int tid = threadIdx.x;
    wa[tid] = W1a[tid];
    wb[tid] = W1b[tid];
    if (tid < 64) { ba[tid] = b1a[tid]; bb[tid] = b1b[tid]; }
    int e0 = blockIdx.x * 16;
    if (tid < 64) {
        int le = tid >> 2, j = tid & 3;
        int e = e0 + le;
        ea[le][j] = (e < N_EDGES) ? edge_attr[e * 4 + j] : 0.f;
    }
    __syncthreads();
    int c = tid & 63;
#pragma unroll
    for (int ch = 0; ch < 4; ch++) {
        int le = (tid >> 6) + ch * 4;
        int e = e0 + le;
        if (e < N_EDGES) {
            float s1 = ba[c], s2 = bb[c];
#pragma unroll
            for (int j = 0; j < 4; j++) {
                s1 += ea[le][j] * wa[j * 64 + c];
                s2 += ea[le][j] * wb[j * 64 + c];
            }
            d_h1e[e * 64 + c] = fmaxf(s1, 0.f);
            d_h2e[e * 64 + c] = fmaxf(s2, 0.f);
            if (c == 0) atomicAdd(&d_deg[edge_index[N_EDGES + e]], 1.f);
            if (c == 1) atomicAdd(&d_srccnt[edge_index[e]], 1);
        }
    }
}

// ---------------- exclusive scan of src counts (single block) ----------------
__global__ void scan_kernel() {
    __shared__ int part[512];
    int tid = threadIdx.x;
    const int CH = (N_NODES + 511) / 512;   // 40
    int base = tid * CH;
    int s = 0;
    for (int j = 0; j < CH; j++) {
        int idx = base + j;
        if (idx < N_NODES) s += d_srccnt[idx];
    }
    part[tid] = s;
    __syncthreads();
    for (int off = 1; off < 512; off <<= 1) {
        int v = (tid >= off) ? part[tid - off] : 0;
        __syncthreads();
        part[tid] += v;
        __syncthreads();
    }
    int run = (tid > 0) ? part[tid - 1] : 0;
    for (int j = 0; j < CH; j++) {
        int idx = base + j;
        if (idx < N_NODES) { d_srcptr[idx] = run; run += d_srccnt[idx]; }
    }
    if (tid == 511) d_srcptr[N_NODES] = run;
}

// ---------------- scatter edges into CSR lists ----------------
__global__ void scatter_kernel(const int* __restrict__ edge_index) {
    int e = blockIdx.x * 256 + threadIdx.x;
    if (e < N_EDGES) {
        int s = edge_index[e];
        int pos = d_srcptr[s] + atomicAdd(&d_fill[s], 1);
        d_elist[pos] = e;
    }
}

// ---------------- W2 tile prefetch (cp.async, 8B) ----------------
template<int IDIM>
__device__ __forceinline__ void stage_w2(const float* __restrict__ W2,
                                         unsigned wss_smem, int kc, int is, int tid) {
    constexpr int WROW = IDIM * 64;
#pragma unroll
    for (int j = 0; j < 8; j++) {
        int p2 = tid + j * NTHR;          // pair index 0..2047
        int o2 = p2 & 31;
        int ks = (p2 >> 5) & 7;
        int ii = p2 >> 8;
        const float* src = W2 + (kc * 8 + ks) * WROW + (is * 8 + ii) * 64 + o2 * 2;
        unsigned dst = wss_smem + (unsigned)((ks * 514 + ii * 64 + o2 * 2) * 4);
        cpa8(dst, src);
    }
}

// ---------------- NNConv: per-NODE weight GEMM (f32x2), k-chunked,
//                  register-accumulated messages with SINGLE atomic commit ----
template<int IDIM>
__launch_bounds__(NTHR, 2)
__global__ void nnconv_kernel(const float* __restrict__ xin_param,
                              const float* __restrict__ W2,
                              const float* __restrict__ b2,
                              const int*   __restrict__ edge_index) {
    const float* xin = (IDIM == 8) ? xin_param : d_h1;
    const float* hE  = (IDIM == 8) ? d_h1e : d_h2e;
    float*       agg = (IDIM == 8) ? d_agg1 : d_agg2;
    const int*   srcp = edge_index;
    const int*   dstp = edge_index + N_EDGES;

    constexpr int IS   = IDIM / 8;   // i-stages per k-chunk
    constexpr int XR   = 36;         // xsT row stride
    constexpr int MKS  = 66;         // Mns per-k stride
    constexpr int MNS  = 8 * MKS;    // 528 per node

    extern __shared__ float sm[];
    float* xsT  = sm;                         // [IDIM][XR]   xsT[i][n]
    float* Wss  = xsT + IDIM * XR;            // [8][514]     staged W2 tile
    float* Mns  = Wss + WBUF;                 // [NT][8k][66] (head reused for b2)
    float* bn   = Mns + NT * MNS;             // [NT][65]
    int*  tasks = (int*)(bn + NT * 65);       // [TCAP]  (ln<<24)|e
    int*  taskD = tasks + TCAP;               // [TCAP]  dst
    int*  sNT   = taskD + TCAP;               // [2]: ntask, csr0

    int tid = threadIdx.x;
    int nb0 = blockIdx.x * NT;
    unsigned wss_base = (unsigned)__cvta_generic_to_shared(Wss);

    // transposed node features
    for (int idx = tid; idx < NT * IDIM; idx += NTHR) {
        int i = idx % IDIM, n = idx / IDIM;
        int gn = nb0 + n;
        xsT[i * XR + n] = (gn < N_NODES) ? xin[gn * IDIM + i] : 0.f;
    }
    if (tid == 0) {
        int c0 = d_srcptr[nb0];
        int hi = nb0 + NT; if (hi > N_NODES) hi = N_NODES;
        sNT[0] = d_srcptr[hi] - c0;
        sNT[1] = c0;
    }
    // stage b2 (flat) into Mns head (free until first Mn store)
    for (int idx = tid; idx < IDIM * 64; idx += NTHR) Mns[idx] = b2[idx];
    __syncthreads();
    int ntask = sNT[0];
    int csr0  = sNT[1];
    // task lists
    for (int t = tid; t < ntask && t < TCAP; t += NTHR) {
        int e = d_elist[csr0 + t];
        tasks[t] = ((srcp[e] - nb0) << 24) | e;
        taskD[t] = dstp[e];
    }
    // bn[n][o] = sum_i xsT[i][n] * b2[i*64+o]
    for (int idx = tid; idx < NT * 64; idx += NTHR) {
        int o = idx & 63, n = idx >> 6;
        float s = 0.f;
#pragma unroll 8
        for (int i = 0; i < IDIM; i++) s += xsT[i * XR + n] * Mns[i * 64 + o];
        bn[n * 65 + o] = s;
    }

    int q  = tid >> 6;       // node oct (warp-uniform): nodes q*8..q*8+7
    int rr = tid & 63;
    int kk = rr >> 3;        // k within chunk
    int oh = rr & 7;         // o octet
    int w = tid >> 5, l = tid & 31;
    int o2 = 2 * l;
    int lim = (ntask < 8 * TMAXW) ? ntask : 8 * TMAXW;

    // per-warp register message accumulators (outputs o2, o2+1 packed)
    unsigned long long accM[TMAXW];
#pragma unroll
    for (int i = 0; i < TMAXW; i++) accM[i] = 0ull;

    for (int kc = 0; kc < 8; kc++) {
        // ---- GEMM: Mn[32n][k=kc*8+kk][64o] over all i ----
        unsigned long long acc[8][4];
#pragma unroll
        for (int a = 0; a < 8; a++)
#pragma unroll
            for (int p = 0; p < 4; p++) acc[a][p] = 0ull;

        for (int is = 0; is < IS; is++) {
            __syncthreads();   // prior-stage Wss readers / prior-kc Mns readers done
            stage_w2<IDIM>(W2, wss_base, kc, is, tid);
            cpa_commit();
            cpa_wait<0>();
            __syncthreads();
#pragma unroll
            for (int ii = 0; ii < 8; ii++) {
                int i = is * 8 + ii;
                const float4* xr = (const float4*)(xsT + i * XR + q * 8);
                float4 xa = xr[0], xb = xr[1];
                unsigned long long h[8];
                h[0] = pack2(xa.x); h[1] = pack2(xa.y); h[2] = pack2(xa.z); h[3] = pack2(xa.w);
                h[4] = pack2(xb.x); h[5] = pack2(xb.y); h[6] = pack2(xb.z); h[7] = pack2(xb.w);
                const unsigned long long* wp =
                    (const unsigned long long*)(Wss + kk * 514 + ii * 64 + oh * 8);
#pragma unroll
                for (int p = 0; p < 4; p++) {
                    unsigned long long wv = wp[p];
                    fma2(acc[0][p], h[0], wv); fma2(acc[1][p], h[1], wv);
                    fma2(acc[2][p], h[2], wv); fma2(acc[3][p], h[3], wv);
                    fma2(acc[4][p], h[4], wv); fma2(acc[5][p], h[5], wv);
                    fma2(acc[6][p], h[6], wv); fma2(acc[7][p], h[7], wv);
                }
            }
        }
        // store Mn chunk (conflict-free)
#pragma unroll
        for (int a = 0; a < 8; a++) {
            unsigned long long* mp =
                (unsigned long long*)(Mns + (q * 8 + a) * MNS + kk * MKS + oh * 8);
#pragma unroll
            for (int p = 0; p < 4; p++) mp[p] = acc[a][p];
        }
        __syncthreads();

        // ---- consume owned tasks into registers (no atomics) ----
        {
            int hb = kc * 8 + (l & 7);
            int pk_n = 0; float hv_n = 0.f;
            if (w < lim) {
                pk_n = tasks[w];
                hv_n = hE[(pk_n & 0xFFFFFF) * 64 + hb];
            }
#pragma unroll
            for (int i = 0; i < TMAXW; i++) {
                int t = w + i * 8;
                if (t >= lim) break;
                int pk = pk_n; float hv = hv_n;
                int tn = t + 8;
                if (tn < lim) {
                    pk_n = tasks[tn];
                    hv_n = hE[(pk_n & 0xFFFFFF) * 64 + hb];
                }
                int ln = pk >> 24;
                const float* mp = Mns + ln * MNS + o2;
#pragma unroll
                for (int k = 0; k < 8; k++) {
                    float hk = __shfl_sync(0xFFFFFFFFu, hv, k);
                    unsigned long long m2 = *(const unsigned long long*)(mp + k * MKS);
                    fma2(accM[i], pack2(hk), m2);
                }
            }
        }
        // ---- overflow tasks (rare): per-chunk atomic path ----
        for (int t = 8 * TMAXW + w; t < ntask; t += 8) {
            int e, ln, d;
            if (t < TCAP) { int pk = tasks[t]; ln = pk >> 24; e = pk & 0xFFFFFF; d = taskD[t]; }
            else { e = d_elist[csr0 + t]; ln = srcp[e] - nb0; d = dstp[e]; }
            float hv = hE[e * 64 + kc * 8 + (l & 7)];
            unsigned long long s2 = 0ull;
            const float* mp = Mns + ln * MNS + o2;
#pragma unroll
            for (int k = 0; k < 8; k++) {
                float hk = __shfl_sync(0xFFFFFFFFu, hv, k);
                fma2(s2, pack2(hk), *(const unsigned long long*)(mp + k * MKS));
            }
            float a0, a1; unpack2(s2, a0, a1);
            if (kc == 0) { a0 += bn[ln * 65 + o2]; a1 += bn[ln * 65 + o2 + 1]; }
            atomicAdd(&agg[d * 64 + o2], a0);
            atomicAdd(&agg[d * 64 + o2 + 1], a1);
        }
    }

    // ---- single commit of register-accumulated messages ----
#pragma unroll
    for (int i = 0; i < TMAXW; i++) {
        int t = w + i * 8;
        if (t >= lim) break;
        int pk = tasks[t];
        int ln = pk >> 24;
        int d  = taskD[t];
        float a0, a1; unpack2(accM[i], a0, a1);
        a0 += bn[ln * 65 + o2];
        a1 += bn[ln * 65 + o2 + 1];
        atomicAdd(&agg[d * 64 + o2], a0);
        atomicAdd(&agg[d * 64 + o2 + 1], a1);
    }
}

// ---------------- node update 1 ----------------
__global__ void node_update1(const float* __restrict__ x,
                             const float* __restrict__ root1,
                             const float* __restrict__ bias1) {
    __shared__ float r1[512], b1s[64], xs[4][8], dn[4];
    int tid = threadIdx.x;
    r1[tid] = root1[tid];
    r1[tid + 256] = root1[tid + 256];
    if (tid < 64) b1s[tid] = bias1[tid];
    int n0 = blockIdx.x * 4;
    if (tid < 32) {
        int ln = tid >> 3, j = tid & 7;
        int n = n0 + ln;
        xs[ln][j] = (n < N_NODES) ? x[n * 8 + j] : 0.f;
    }
    if (tid < 4) {
        int n = n0 + tid;
        dn[tid] = (n < N_NODES) ? fmaxf(d_deg[n], 1.f) : 1.f;
    }
    __syncthreads();
    int c = tid & 63, ln = tid >> 6, n = n0 + ln;
    if (n < N_NODES) {
        float s = d_agg1[n * 64 + c] / dn[ln] + b1s[c];
#pragma unroll
        for (int j = 0; j < 8; j++) s += xs[ln][j] * r1[j * 64 + c];
        d_h1[n * 64 + c] = fmaxf(s, 0.f);
    }
}

// ---------------- node update 2 + column sums for mean pool ----------------
__global__ void node_update2(const float* __restrict__ root2,
                             const float* __restrict__ bias2) {
    __shared__ float h1s[64 * 65];
    __shared__ float r2s[64 * 64];
    __shared__ float b2s[64];
    __shared__ float dn[64];
    __shared__ float colpart[4 * 64];
    int tid = threadIdx.x;
    int n0 = blockIdx.x * 64;
    for (int idx = tid; idx < 64 * 64; idx += 256) r2s[idx] = root2[idx];
    for (int idx = tid; idx < 64 * 64; idx += 256) {
        int ln = idx >> 6, kk = idx & 63;
        int n = n0 + ln;
        h1s[ln * 65 + kk] = (n < N_NODES) ? d_h1[n * 64 + kk] : 0.f;
    }
    if (tid < 64) {
        b2s[tid] = bias2[tid];
        int n = n0 + tid;
        dn[tid] = (n < N_NODES) ? fmaxf(d_deg[n], 1.f) : 1.f;
    }
    __syncthreads();
    int c = tid & 63, ng = tid >> 6;
    float csum = 0.f;
    for (int j = 0; j < 16; j++) {
        int ln = ng + 4 * j;
        int n = n0 + ln;
        if (n < N_NODES) {
            float s = d_agg2[n * 64 + c] / dn[ln] + b2s[c];
#pragma unroll 8
            for (int kk = 0; kk < 64; kk++) s += h1s[ln * 65 + kk] * r2s[kk * 64 + c];
            csum += fmaxf(s, 0.f);
        }
    }
    colpart[ng * 64 + c] = csum;
    __syncthreads();
    if (tid < 64) {
        float t = colpart[tid] + colpart[64 + tid] + colpart[128 + tid] + colpart[192 + tid];
        atomicAdd(&d_colsum[tid], t);
    }
}

// ---------------- g vector ----------------
__global__ void g_kernel(const float* __restrict__ projW, const float* __restrict__ projb) {
    __shared__ float cs[64];
    int tid = threadIdx.x;
    cs[tid] = d_colsum[tid] * (1.f / (float)N_NODES);
    __syncthreads();
    float s = projb[tid];
    for (int c = 0; c < 64; c++) s += cs[c] * projW[c * 64 + tid];
    d_g[tid] = s;
}

// ---------------- MLP layer 1 (split-K, f32x2) ----------------
__global__ void mlp1_main(const float* __restrict__ a, const float* __restrict__ mW1) {
    __shared__ __align__(16) float aT[64 * 36];
    __shared__ __align__(16) float Wt[64 * 132];
    int tid = threadIdx.x;
    int m0 = blockIdx.x * 32;
    int ks = blockIdx.y * 313;
    int ke = min(N_ACT, ks + 313);
    int tj = tid & 31, tb = tid >> 5;
    int j0 = tj * 4, b0 = tb * 4;
    unsigned long long acc2[4][2];
#pragma unroll
    for (int p = 0; p < 4; p++) { acc2[p][0] = 0ull; acc2[p][1] = 0ull; }

    for (int kkb = ks; kkb < ke; kkb += 64) {
        int klen = ke - kkb;
        __syncthreads();
        for (int idx = tid; idx < 2048; idx += 256) {
            int b = idx >> 6, k = idx & 63;
            aT[k * 36 + b] = (k < klen) ? a[(m0 + b) * N_ACT + kkb + k] : 0.f;
        }
        for (int idx = tid; idx < 8192; idx += 256) {
            int k = idx >> 7, j = idx & 127;
            Wt[k * 132 + j] = (k < klen) ? mW1[(kkb + k) * 128 + j] : 0.f;
        }
        __syncthreads();
#pragma unroll 8
        for (int k = 0; k < 64; k++) {
            float4 av = *(const float4*)&aT[k * 36 + b0];
            const unsigned long long* wp = (const unsigned long long*)&Wt[k * 132 + j0];
            unsigned long long w0 = wp[0], w1 = wp[1];
            unsigned long long a0 = pack2(av.x), a1 = pack2(av.y);
            unsigned long long a2 = pack2(av.z), a3 = pack2(av.w);
            fma2(acc2[0][0], a0, w0); fma2(acc2[0][1], a0, w1);
            fma2(acc2[1][0], a1, w0); fma2(acc2[1][1], a1, w1);
            fma2(acc2[2][0], a2, w0); fma2(acc2[2][1], a2, w1);
            fma2(acc2[3][0], a3, w0); fma2(acc2[3][1], a3, w1);
        }
    }
#pragma unroll
    for (int p = 0; p < 4; p++) {
        float v0, v1, v2, v3;
        unpack2(acc2[p][0], v0, v1);
        unpack2(acc2[p][1], v2, v3);
        float* yp = &d_y1[(m0 + b0 + p) * 128 + j0];
        atomicAdd(yp + 0, v0);
        atomicAdd(yp + 1, v1);
        atomicAdd(yp + 2, v2);
        atomicAdd(yp + 3, v3);
    }
}

__global__ void mlp1_finish(const float* __restrict__ mW1, const float* __restrict__ mb1) {
    __shared__ float gs[64];
    int tid = threadIdx.x;
    if (tid < 64) gs[tid] = d_g[tid];
    __syncthreads();
    int idx = blockIdx.x * 256 + tid;
    int j = idx & 127;
    float s = d_y1[idx] + mb1[j];
    for (int c = 0; c < 64; c++) s += gs[c] * mW1[(N_ACT + c) * 128 + j];
    d_z1[idx] = fmaxf(s, 0.f);
}

__global__ void mlp2_kernel(const float* __restrict__ mW2, const float* __restrict__ mb2) {
    __shared__ float zs[2][128];
    int tid = threadIdx.x;
    int b0 = blockIdx.x * 2;
    zs[tid >> 7][tid & 127] = d_z1[b0 * 128 + tid];
    __syncthreads();
    int lb = tid >> 7, j = tid & 127;
    float s = mb2[j];
#pragma unroll 4
    for (int k = 0; k < 128; k++) s += zs[lb][k] * mW2[k * 128 + j];
    d_z2[(b0 + lb) * 128 + j] = fmaxf(s, 0.f);
}

__global__ void mlp3_kernel(const float* __restrict__ mW3, const float* __restrict__ mb3,
                            float* __restrict__ out) {
    __shared__ float w3[128];
    int tid = threadIdx.x;
    if (tid < 128) w3[tid] = mW3[tid];
    __syncthreads();
    float s = mb3[0];
    for (int j = 0; j < 128; j++) s += d_z2[tid * 128 + j] * w3[j];
    out[tid] = s;
}

// ---------------- launcher ----------------
extern "C" void kernel_launch(void* const* d_in, const int* in_sizes, int n_in,
                              void* d_out, int out_size) {
    const float* x     = (const float*)d_in[0];
    const int*   ei    = (const int*)  d_in[1];
    const float* ea    = (const float*)d_in[2];
    const float* a     = (const float*)d_in[3];
    const float* e1W1  = (const float*)d_in[4];
    const float* e1b1  = (const float*)d_in[5];
    const float* e1W2  = (const float*)d_in[6];
    const float* e1b2  = (const float*)d_in[7];
    const float* root1 = (const float*)d_in[8];
    const float* bias1 = (const float*)d_in[9];
    const float* e2W1  = (const float*)d_in[10];
    const float* e2b1  = (const float*)d_in[11];
    const float* e2W2  = (const float*)d_in[12];
    const float* e2b2  = (const float*)d_in[13];
    const float* root2 = (const float*)d_in[14];
    const float* bias2 = (const float*)d_in[15];
    const float* projW = (const float*)d_in[16];
    const float* projb = (const float*)d_in[17];
    const float* mW1   = (const float*)d_in[18];
    const float* mb1   = (const float*)d_in[19];
    const float* mW2   = (const float*)d_in[20];
    const float* mb2   = (const float*)d_in[21];
    const float* mW3   = (const float*)d_in[22];
    const float* mb3   = (const float*)d_in[23];
    float* out = (float*)d_out;

    // smem (floats): xsT + Wss(4112) + Mns(32*528) + bn(32*65) + tasks + taskD + 2
    const int sbase = (WBUF + NT * 528 + NT * 65 + TCAP + TCAP + 2);
    const int s8  = (8  * 36 + sbase) * 4;   //  95,560 B
    const int s64 = (64 * 36 + sbase) * 4;   // 103,624 B  -> 2 blocks/SM
    cudaFuncSetAttribute(nnconv_kernel<8>,  cudaFuncAttributeMaxDynamicSharedMemorySize, s8);
    cudaFuncSetAttribute(nnconv_kernel<64>, cudaFuncAttributeMaxDynamicSharedMemorySize, s64);

    const int NB = (N_NODES + NT - 1) / NT;   // 625

    zero_kernel<<<512, 256>>>();
    edge_feat_kernel<<<(N_EDGES + 15) / 16, 256>>>(ea, ei, e1W1, e1b1, e2W1, e2b1);
    scan_kernel<<<1, 512>>>();
    scatter_kernel<<<(N_EDGES + 255) / 256, 256>>>(ei);
    nnconv_kernel<8><<<NB, NTHR, s8>>>(x, e1W2, e1b2, ei);
    node_update1<<<(N_NODES + 3) / 4, 256>>>(x, root1, bias1);
    nnconv_kernel<64><<<NB, NTHR, s64>>>(x, e2W2, e2b2, ei);
    node_update2<<<(N_NODES + 63) / 64, 256>>>(root2, bias2);
    g_kernel<<<1, 64>>>(projW, projb);
    mlp1_main<<<dim3(8, 64), 256>>>(a, mW1);
    mlp1_finish<<<128, 256>>>(mW1, mb1);
    mlp2_kernel<<<128, 256>>>(mW2, mb2);
    mlp3_kernel<<<1, 256>>>(mW3, mb3, out);
}